// round 8
// baseline (speedup 1.0000x reference)
#include <cuda_runtime.h>
#include <cuda_fp16.h>
#include <cstdint>
#include <cstddef>

// Problem constants
#define DM 1024
#define FF 4096
#define MROWS 4096          // B*S = 2*2048
#define EPS 1e-5f

// ---------------------------------------------------------------------------
// Scratch (static device globals; no runtime allocation)
// ---------------------------------------------------------------------------
__device__ __half g_xh[MROWS * DM];     // half(x)               (8 MB)
__device__ __half g_Wvh[DM * DM];       // half(Wv)              (2 MB)
__device__ __half g_Woh[DM * DM];       // half(Wo)              (2 MB)
__device__ __half g_W1h[DM * FF];       // half(W1)              (8 MB)
__device__ __half g_W2h[FF * DM];       // half(W2)              (8 MB)
__device__ __half g_Wvoh[DM * DM];      // half(Wv@Wo)           (2 MB)
__device__ float  g_bvo[DM];            // bv @ Wo + bo
__device__ float  g_bvop[8 * DM];       // bvo k-split partials
__device__ float  g_attn[4 * DM * DM];  // fold split-K partials, then x@Wvo+bvo (16 MB)
__device__ float  g_h[MROWS * DM];      // LN1 output (f32)      (16 MB)
__device__ __half g_hh[MROWS * DM];     // LN1 output (half)     (8 MB)
__device__ __half g_ffh[MROWS * FF];    // relu(h@W1+b1) half    (32 MB)
__device__ float  g_ff2[MROWS * DM];    // ff@W2+b2              (16 MB)

// ---------------------------------------------------------------------------
// helpers
// ---------------------------------------------------------------------------
__device__ __forceinline__ uint32_t smem_u32(const void* p) {
    uint32_t a;
    asm("{ .reg .u64 t; cvta.to.shared.u64 t, %1; cvt.u32.u64 %0, t; }"
        : "=r"(a) : "l"(p));
    return a;
}

__device__ __forceinline__ void cp16(uint32_t s, const void* g) {
    asm volatile("cp.async.cg.shared.global [%0], [%1], 16;" :: "r"(s), "l"(g) : "memory");
}

// SMEM geometry (halfs). Padding keeps ldmatrix conflict-free:
//  A stride 40 halfs = 80B: 16B-seg index 5r mod 8, all 8 distinct
//  B stride 264 halfs = 528B: 33r mod 8 == r mod 8, all 8 distinct
#define ASTR 40
#define BSTR 264
#define ABYTES (128 * ASTR * 2)             // 10240
#define BBYTES (32 * BSTR * 2)              // 16896
#define STAGEB (ABYTES + BBYTES)            // 27136
#define NSTAGE 5
#define SMEM_TOTAL (NSTAGE * STAGEB)        // 135680 (1 CTA/SM)

// ---------------------------------------------------------------------------
// fp16 mma.sync GEMM: C[M,N] = A[M,K] @ B[K,N] (+ bias[N]) (+ReLU)
// Tile 128(M) x 256(N), BK=32. 256 threads = 8 warps (2 M x 4 N),
// warp tile 64x64 = 4x8 m16n8k16. 5-stage cp.async (4 in flight), 1 CTA/SM.
// NSPLIT>1: blockIdx.z selects K-chunk and a distinct f32 output buffer.
// ---------------------------------------------------------------------------
template <int RELU, int NSPLIT, int OUTH>
__global__ __launch_bounds__(256, 1)
void hgemm(const __half* __restrict__ A, const __half* __restrict__ B,
           const float* __restrict__ bias, void* __restrict__ Cv,
           int M, int N, int K) {
    extern __shared__ __align__(16) char smem_raw[];
    const uint32_t sbase = smem_u32(smem_raw);

    int k0g = 0, klen = K;
    float* Cf = (float*)Cv;
    if (NSPLIT > 1) {
        klen = K / NSPLIT;
        k0g = blockIdx.z * klen;
        Cf += (size_t)blockIdx.z * M * N;
    }

    const int tid  = threadIdx.x;
    const int wid  = tid >> 5, lane = tid & 31;
    const int g    = lane >> 2, tig = lane & 3;
    const int wm   = wid >> 2, wn = wid & 3;        // 2 x 4 warp grid
    const int bm   = blockIdx.y * 128, bn = blockIdx.x * 256;
    const int nk   = klen >> 5;

    // producer: A 128x32 halfs (512 16B chunks), B 32x256 halfs (1024 chunks)
    auto load_stage = [&](int kt, int st) {
        const uint32_t sa = sbase + (uint32_t)st * STAGEB;
        const uint32_t sb = sa + ABYTES;
        const int kk = k0g + (kt << 5);
#pragma unroll
        for (int i = 0; i < 2; ++i) {
            int c = tid + i * 256;
            int r = c >> 2, s = c & 3;                 // row 0..127, seg 0..3
            cp16(sa + (uint32_t)(r * (ASTR * 2) + s * 16),
                 A + (size_t)(bm + r) * K + kk + s * 8);
        }
#pragma unroll
        for (int i = 0; i < 4; ++i) {
            int c = tid + i * 256;
            int r = c >> 5, s = c & 31;                // row 0..31, seg 0..31
            cp16(sb + (uint32_t)(r * (BSTR * 2) + s * 16),
                 B + (size_t)(kk + r) * N + bn + s * 8);
        }
        asm volatile("cp.async.commit_group;" ::: "memory");
    };

    const uint32_t a_row  = (uint32_t)(lane & 15);
    const uint32_t a_colk = (uint32_t)((lane >> 4) * 8);
    const uint32_t b_krow = (uint32_t)(lane & 15);
    const uint32_t b_coln = (uint32_t)((lane >> 4) * 8);

    float acc[4][8][4];
#pragma unroll
    for (int i = 0; i < 4; ++i)
#pragma unroll
        for (int j = 0; j < 8; ++j)
#pragma unroll
            for (int q = 0; q < 4; ++q) acc[i][j][q] = 0.f;

    load_stage(0, 0);
    load_stage(1, 1);
    load_stage(2, 2);
    load_stage(3, 3);

    int cst = 0;        // current stage index (mod 5)
    for (int kt = 0; kt < nk; ++kt) {
        const int rem = nk - 1 - kt;    // loads still outstanding beyond this tile
        if (rem >= 3)      asm volatile("cp.async.wait_group 3;" ::: "memory");
        else if (rem == 2) asm volatile("cp.async.wait_group 2;" ::: "memory");
        else if (rem == 1) asm volatile("cp.async.wait_group 1;" ::: "memory");
        else               asm volatile("cp.async.wait_group 0;" ::: "memory");
        __syncthreads();

        const uint32_t sa = sbase + (uint32_t)cst * STAGEB;
        const uint32_t sb = sa + ABYTES;

#pragma unroll
        for (int ks = 0; ks < 2; ++ks) {               // two k16 steps per BK=32
            uint32_t a[4][4], b[8][2];
#pragma unroll
            for (int mi = 0; mi < 4; ++mi) {
                const uint32_t addr = sa +
                    ((uint32_t)(wm * 64 + mi * 16) + a_row) * (ASTR * 2) +
                    ((uint32_t)(ks * 16) + a_colk) * 2;
                asm volatile(
                    "ldmatrix.sync.aligned.m8n8.x4.shared.b16 {%0,%1,%2,%3}, [%4];"
                    : "=r"(a[mi][0]), "=r"(a[mi][1]), "=r"(a[mi][2]), "=r"(a[mi][3])
                    : "r"(addr));
            }
#pragma unroll
            for (int njp = 0; njp < 4; ++njp) {        // each x4.trans covers 2 nj
                const uint32_t addr = sb +
                    ((uint32_t)(ks * 16) + b_krow) * (BSTR * 2) +
                    ((uint32_t)(wn * 64 + njp * 16) + b_coln) * 2;
                asm volatile(
                    "ldmatrix.sync.aligned.m8n8.x4.trans.shared.b16 {%0,%1,%2,%3}, [%4];"
                    : "=r"(b[njp * 2][0]), "=r"(b[njp * 2][1]),
                      "=r"(b[njp * 2 + 1][0]), "=r"(b[njp * 2 + 1][1])
                    : "r"(addr));
            }
#pragma unroll
            for (int mi = 0; mi < 4; ++mi)
#pragma unroll
                for (int nj = 0; nj < 8; ++nj)
                    asm volatile(
                        "mma.sync.aligned.m16n8k16.row.col.f32.f16.f16.f32 "
                        "{%0,%1,%2,%3}, {%4,%5,%6,%7}, {%8,%9}, {%0,%1,%2,%3};"
                        : "+f"(acc[mi][nj][0]), "+f"(acc[mi][nj][1]),
                          "+f"(acc[mi][nj][2]), "+f"(acc[mi][nj][3])
                        : "r"(a[mi][0]), "r"(a[mi][1]), "r"(a[mi][2]), "r"(a[mi][3]),
                          "r"(b[nj][0]), "r"(b[nj][1]));
        }
        if (kt + 4 < nk) load_stage(kt + 4, (cst + 4 >= NSTAGE) ? cst - 1 : cst + 4);
        if (++cst == NSTAGE) cst = 0;
    }

    // epilogue: c0,c1 at (row g, cols 2tig,2tig+1); c2,c3 at row g+8
#pragma unroll
    for (int mi = 0; mi < 4; ++mi) {
        const int r0 = bm + wm * 64 + mi * 16 + g;
#pragma unroll
        for (int nj = 0; nj < 8; ++nj) {
            const int c0 = bn + wn * 64 + nj * 8 + tig * 2;
            float bx = 0.f, by = 0.f;
            if (bias) { bx = bias[c0]; by = bias[c0 + 1]; }
            float v0 = acc[mi][nj][0] + bx, v1 = acc[mi][nj][1] + by;
            float v2 = acc[mi][nj][2] + bx, v3 = acc[mi][nj][3] + by;
            if (RELU) {
                v0 = fmaxf(v0, 0.f); v1 = fmaxf(v1, 0.f);
                v2 = fmaxf(v2, 0.f); v3 = fmaxf(v3, 0.f);
            }
            if (OUTH) {
                __half* Ch = (__half*)Cv;
                *(__half2*)(Ch + (size_t)r0 * N + c0)       = __floats2half2_rn(v0, v1);
                *(__half2*)(Ch + (size_t)(r0 + 8) * N + c0) = __floats2half2_rn(v2, v3);
            } else {
                *(float2*)(Cf + (size_t)r0 * N + c0)       = make_float2(v0, v1);
                *(float2*)(Cf + (size_t)(r0 + 8) * N + c0) = make_float2(v2, v3);
            }
        }
    }
}

// ---------------------------------------------------------------------------
// out[i] = half(in[i])  (float4 -> 4 halfs)
// ---------------------------------------------------------------------------
__global__ void f2h_kernel(const float* __restrict__ in, __half* __restrict__ out) {
    const int i = blockIdx.x * blockDim.x + threadIdx.x;
    float4 v = ((const float4*)in)[i];
    ((__half2*)out)[2 * i]     = __floats2half2_rn(v.x, v.y);
    ((__half2*)out)[2 * i + 1] = __floats2half2_rn(v.z, v.w);
}

// ---------------------------------------------------------------------------
// c[i] = half(p0[i]+p1[i]+p2[i]+p3[i])  (split-K=4 combine for Wvo)
// ---------------------------------------------------------------------------
__global__ void comb4h_kernel(const float* __restrict__ p, __half* __restrict__ c) {
    const int i = blockIdx.x * blockDim.x + threadIdx.x;
    const size_t st = (size_t)DM * DM / 4;     // in float4 units
    float4 v0 = ((const float4*)p)[i];
    float4 v1 = ((const float4*)p)[i + st];
    float4 v2 = ((const float4*)p)[i + 2 * st];
    float4 v3 = ((const float4*)p)[i + 3 * st];
    float a = (v0.x + v1.x) + (v2.x + v3.x);
    float b = (v0.y + v1.y) + (v2.y + v3.y);
    float d = (v0.z + v1.z) + (v2.z + v3.z);
    float e = (v0.w + v1.w) + (v2.w + v3.w);
    ((__half2*)c)[2 * i]     = __floats2half2_rn(a, b);
    ((__half2*)c)[2 * i + 1] = __floats2half2_rn(d, e);
}

// ---------------------------------------------------------------------------
// bvo = bv @ Wo + bo, two-stage k-split (deterministic, f32)
// ---------------------------------------------------------------------------
__global__ void bvo_part_kernel(const float* __restrict__ bv, const float* __restrict__ Wo,
                                float* __restrict__ part) {
    const int n = blockIdx.x * 128 + threadIdx.x;
    const int kc = blockIdx.y;
    float s = 0.f;
#pragma unroll 4
    for (int k = kc * 128; k < kc * 128 + 128; ++k)
        s += bv[k] * Wo[(size_t)k * DM + n];
    part[kc * DM + n] = s;
}
__global__ void bvo_comb_kernel(const float* __restrict__ part, const float* __restrict__ bo,
                                float* __restrict__ bvo) {
    const int n = blockIdx.x * 256 + threadIdx.x;
    float s = bo[n];
#pragma unroll
    for (int j = 0; j < 8; ++j) s += part[j * DM + n];
    bvo[n] = s;
}

// ---------------------------------------------------------------------------
// out[row] = LayerNorm(res[row] + add[row]) * gamma + beta (f32),
// optional half copy for downstream GEMM A operand.
// ---------------------------------------------------------------------------
__global__ __launch_bounds__(256)
void add_ln_kernel(const float* __restrict__ res, const float* __restrict__ add,
                   const float* __restrict__ gamma, const float* __restrict__ beta,
                   float* __restrict__ out, __half* __restrict__ out_h) {
    const int row = blockIdx.x;
    const int t = threadIdx.x;
    const float4 r = ((const float4*)(res + (size_t)row * DM))[t];
    const float4 a = ((const float4*)(add + (size_t)row * DM))[t];
    float v0 = r.x + a.x, v1 = r.y + a.y, v2 = r.z + a.z, v3 = r.w + a.w;

    float s  = v0 + v1 + v2 + v3;
    float ss = v0 * v0 + v1 * v1 + v2 * v2 + v3 * v3;
#pragma unroll
    for (int o = 16; o > 0; o >>= 1) {
        s  += __shfl_xor_sync(0xFFFFFFFFu, s, o);
        ss += __shfl_xor_sync(0xFFFFFFFFu, ss, o);
    }
    __shared__ float sh_s[8], sh_ss[8];
    const int w = t >> 5, l = t & 31;
    if (l == 0) { sh_s[w] = s; sh_ss[w] = ss; }
    __syncthreads();
    if (w == 0) {
        s  = (l < 8) ? sh_s[l]  : 0.f;
        ss = (l < 8) ? sh_ss[l] : 0.f;
#pragma unroll
        for (int o = 4; o > 0; o >>= 1) {
            s  += __shfl_xor_sync(0xFFFFFFFFu, s, o);
            ss += __shfl_xor_sync(0xFFFFFFFFu, ss, o);
        }
        if (l == 0) { sh_s[0] = s; sh_ss[0] = ss; }
    }
    __syncthreads();
    const float mean = sh_s[0] * (1.f / DM);
    const float var  = sh_ss[0] * (1.f / DM) - mean * mean;
    const float inv  = rsqrtf(var + EPS);

    const float4 gg = ((const float4*)gamma)[t];
    const float4 bb = ((const float4*)beta)[t];
    float4 o4;
    o4.x = (v0 - mean) * inv * gg.x + bb.x;
    o4.y = (v1 - mean) * inv * gg.y + bb.y;
    o4.z = (v2 - mean) * inv * gg.z + bb.z;
    o4.w = (v3 - mean) * inv * gg.w + bb.w;
    ((float4*)(out + (size_t)row * DM))[t] = o4;
    if (out_h) {
        __half2* oh = (__half2*)(out_h + (size_t)row * DM);
        oh[2 * t]     = __floats2half2_rn(o4.x, o4.y);
        oh[2 * t + 1] = __floats2half2_rn(o4.z, o4.w);
    }
}

// ---------------------------------------------------------------------------
// Launch. Diagonal-only mask => attention == V projection. Layer reduces to:
//   attn = x @ (Wv@Wo) + (bv@Wo + bo)
//   h    = LN(x + attn; g1, beta1)
//   out  = LN(h + relu(h@W1+b1)@W2 + b2; g2, beta2)
// ---------------------------------------------------------------------------
extern "C" void kernel_launch(void* const* d_in, const int* in_sizes, int n_in,
                              void* d_out, int out_size) {
    const float* x   = (const float*)d_in[0];
    const float* Wv  = (const float*)d_in[6];
    const float* bv  = (const float*)d_in[7];
    const float* Wo  = (const float*)d_in[8];
    const float* bo  = (const float*)d_in[9];
    const float* W1  = (const float*)d_in[10];
    const float* b1  = (const float*)d_in[11];
    const float* W2  = (const float*)d_in[12];
    const float* b2  = (const float*)d_in[13];
    const float* g1  = (const float*)d_in[14];
    const float* be1 = (const float*)d_in[15];
    const float* g2  = (const float*)d_in[16];
    const float* be2 = (const float*)d_in[17];
    float* out = (float*)d_out;

    __half *xh, *Wvh, *Woh, *W1h, *W2h, *Wvoh, *hh, *ffh;
    float *bvo, *bvop, *attn, *h, *ff2;
    cudaGetSymbolAddress((void**)&xh,   g_xh);
    cudaGetSymbolAddress((void**)&Wvh,  g_Wvh);
    cudaGetSymbolAddress((void**)&Woh,  g_Woh);
    cudaGetSymbolAddress((void**)&W1h,  g_W1h);
    cudaGetSymbolAddress((void**)&W2h,  g_W2h);
    cudaGetSymbolAddress((void**)&Wvoh, g_Wvoh);
    cudaGetSymbolAddress((void**)&hh,   g_hh);
    cudaGetSymbolAddress((void**)&ffh,  g_ffh);
    cudaGetSymbolAddress((void**)&bvo,  g_bvo);
    cudaGetSymbolAddress((void**)&bvop, g_bvop);
    cudaGetSymbolAddress((void**)&attn, g_attn);
    cudaGetSymbolAddress((void**)&h,    g_h);
    cudaGetSymbolAddress((void**)&ff2,  g_ff2);

    static bool attr_done = false;
    if (!attr_done) {
        cudaFuncSetAttribute(hgemm<0, 1, 0>, cudaFuncAttributeMaxDynamicSharedMemorySize, SMEM_TOTAL);
        cudaFuncSetAttribute(hgemm<1, 1, 1>, cudaFuncAttributeMaxDynamicSharedMemorySize, SMEM_TOTAL);
        cudaFuncSetAttribute(hgemm<0, 4, 0>, cudaFuncAttributeMaxDynamicSharedMemorySize, SMEM_TOTAL);
        attr_done = true;
    }

    // fp16 operand conversion (off the GEMM critical loop)
    f2h_kernel<<<(DM * DM / 4) / 256, 256>>>(Wv, Wvh);
    f2h_kernel<<<(DM * DM / 4) / 256, 256>>>(Wo, Woh);
    f2h_kernel<<<(DM * FF / 4) / 256, 256>>>(W1, W1h);
    f2h_kernel<<<(FF * DM / 4) / 256, 256>>>(W2, W2h);
    f2h_kernel<<<(MROWS * DM / 4) / 256, 256>>>(x, xh);

    // bvo = bv @ Wo + bo (f32, deterministic)
    bvo_part_kernel<<<dim3(DM / 128, 8), 128>>>(bv, Wo, bvop);
    bvo_comb_kernel<<<DM / 256, 256>>>(bvop, bo, bvo);

    // Wvoh = half(Wv @ Wo), split-K=4; f32 partials in g_attn scratch
    hgemm<0, 4, 0><<<dim3(DM / 256, DM / 128, 4), 256, SMEM_TOTAL>>>(
        Wvh, Woh, nullptr, attn, DM, DM, DM);
    comb4h_kernel<<<(DM * DM / 4) / 256, 256>>>(attn, Wvoh);

    // attn = xh @ Wvoh + bvo  (f32 out; reuses scratch after combine)
    hgemm<0, 1, 0><<<dim3(DM / 256, MROWS / 128), 256, SMEM_TOTAL>>>(
        xh, Wvoh, bvo, attn, MROWS, DM, DM);

    // h = LN(x + attn); hh = half(h)
    add_ln_kernel<<<MROWS, 256>>>(x, attn, g1, be1, h, hh);

    // ffh = half(relu(hh @ W1h + b1))
    hgemm<1, 1, 1><<<dim3(FF / 256, MROWS / 128), 256, SMEM_TOTAL>>>(
        hh, W1h, b1, ffh, MROWS, FF, DM);

    // ff2 = ffh @ W2h + b2
    hgemm<0, 1, 0><<<dim3(DM / 256, MROWS / 128), 256, SMEM_TOTAL>>>(
        ffh, W2h, b2, ff2, MROWS, DM, FF);

    // out = LN(h + ff2)
    add_ln_kernel<<<MROWS, 256>>>(h, ff2, g2, be2, out, nullptr);
}

// round 9
// speedup vs baseline: 1.1718x; 1.1718x over previous
#include <cuda_runtime.h>
#include <cuda_fp16.h>
#include <cstdint>
#include <cstddef>

// Problem constants
#define DM 1024
#define FF 4096
#define MROWS 4096          // B*S = 2*2048
#define EPS 1e-5f

// ---------------------------------------------------------------------------
// Scratch (static device globals; no runtime allocation)
// ---------------------------------------------------------------------------
__device__ __half g_xh[MROWS * DM];     // half(x)               (8 MB)
__device__ __half g_Wvh[DM * DM];       // half(Wv)              (2 MB)
__device__ __half g_Woh[DM * DM];       // half(Wo)              (2 MB)
__device__ __half g_W1h[DM * FF];       // half(W1)              (8 MB)
__device__ __half g_W2h[FF * DM];       // half(W2)              (8 MB)
__device__ __half g_Wvoh[DM * DM];      // half(Wv@Wo)           (2 MB)
__device__ float  g_bvo[DM];            // bv @ Wo + bo
__device__ float  g_bvop[8 * DM];       // bvo k-split partials
__device__ float  g_attn[4 * DM * DM];  // fold split-K partials, then x@Wvo+bvo (16 MB)
__device__ float  g_h[MROWS * DM];      // LN1 output (f32)      (16 MB)
__device__ __half g_hh[MROWS * DM];     // LN1 output (half)     (8 MB)
__device__ __half g_ffh[MROWS * FF];    // relu(h@W1+b1) half    (32 MB)
__device__ float  g_ff2[MROWS * DM];    // ff@W2+b2              (16 MB)

// ---------------------------------------------------------------------------
// helpers
// ---------------------------------------------------------------------------
__device__ __forceinline__ uint32_t smem_u32(const void* p) {
    uint32_t a;
    asm("{ .reg .u64 t; cvta.to.shared.u64 t, %1; cvt.u32.u64 %0, t; }"
        : "=r"(a) : "l"(p));
    return a;
}

__device__ __forceinline__ void cp16(uint32_t s, const void* g) {
    asm volatile("cp.async.cg.shared.global [%0], [%1], 16;" :: "r"(s), "l"(g) : "memory");
}

// SMEM geometry (halfs). Padding keeps ldmatrix conflict-free:
//  A stride 40 halfs = 80B: 16B-seg index 5r mod 8, all 8 distinct
//  B stride 136 halfs = 272B: 17r mod 8 == r mod 8, all 8 distinct
#define ASTR 40
#define BSTR 136
#define ABYTES (128 * ASTR * 2)             // 10240
#define BBYTES (32 * BSTR * 2)              // 8704
#define STAGEB (ABYTES + BBYTES)            // 18944
#define NSTAGE 4
#define SMEM_TOTAL (NSTAGE * STAGEB)        // 75776  (x2 CTAs/SM = 151552)

// ---------------------------------------------------------------------------
// fp16 mma.sync GEMM: C[M,N] = A[M,K] @ B[K,N] (+ bias[N]) (+ReLU)
// A, B half row-major; C float (or half when OUTH=1). Tile 128x128, BK=32.
// 256 threads = 8 warps (2 M x 4 N), warp tile 64x32 = 4x4 m16n8k16.
// 4-stage cp.async pipeline (3 in flight), 2 CTAs/SM.
// NSPLIT>1: blockIdx.z selects K-chunk and a distinct f32 output buffer.
// ---------------------------------------------------------------------------
template <int RELU, int NSPLIT, int OUTH>
__global__ __launch_bounds__(256, 2)
void hgemm(const __half* __restrict__ A, const __half* __restrict__ B,
           const float* __restrict__ bias, void* __restrict__ Cv,
           int M, int N, int K) {
    extern __shared__ __align__(16) char smem_raw[];
    const uint32_t sbase = smem_u32(smem_raw);

    int k0g = 0, klen = K;
    float* Cf = (float*)Cv;
    if (NSPLIT > 1) {
        klen = K / NSPLIT;
        k0g = blockIdx.z * klen;
        Cf += (size_t)blockIdx.z * M * N;
    }

    const int tid  = threadIdx.x;
    const int wid  = tid >> 5, lane = tid & 31;
    const int g    = lane >> 2, tig = lane & 3;
    const int wm   = wid >> 2, wn = wid & 3;        // 2 x 4 warp grid
    const int bm   = blockIdx.y * 128, bn = blockIdx.x * 128;
    const int nk   = klen >> 5;

    // producer: A 128x32 halfs = 512 x16B chunks; B 32x128 halfs = 512 chunks
    auto load_stage = [&](int kt, int st) {
        const uint32_t sa = sbase + (uint32_t)st * STAGEB;
        const uint32_t sb = sa + ABYTES;
        const int kk = k0g + (kt << 5);
#pragma unroll
        for (int i = 0; i < 2; ++i) {
            int c = tid + i * 256;
            int r = c >> 2, s = c & 3;                 // row 0..127, seg 0..3 (8 halfs)
            cp16(sa + (uint32_t)(r * (ASTR * 2) + s * 16),
                 A + (size_t)(bm + r) * K + kk + s * 8);
        }
#pragma unroll
        for (int i = 0; i < 2; ++i) {
            int c = tid + i * 256;
            int r = c >> 4, s = c & 15;                // row 0..31, seg 0..15
            cp16(sb + (uint32_t)(r * (BSTR * 2) + s * 16),
                 B + (size_t)(kk + r) * N + bn + s * 8);
        }
        asm volatile("cp.async.commit_group;" ::: "memory");
    };

    const uint32_t a_row  = (uint32_t)(lane & 15);
    const uint32_t a_colk = (uint32_t)((lane >> 4) * 8);
    const uint32_t b_krow = (uint32_t)(lane & 15);
    const uint32_t b_coln = (uint32_t)((lane >> 4) * 8);

    float acc[4][4][4];
#pragma unroll
    for (int i = 0; i < 4; ++i)
#pragma unroll
        for (int j = 0; j < 4; ++j)
#pragma unroll
            for (int q = 0; q < 4; ++q) acc[i][j][q] = 0.f;

    load_stage(0, 0);
    load_stage(1, 1);
    load_stage(2, 2);

    for (int kt = 0; kt < nk; ++kt) {
        if (kt < nk - 2)       asm volatile("cp.async.wait_group 2;" ::: "memory");
        else if (kt == nk - 2) asm volatile("cp.async.wait_group 1;" ::: "memory");
        else                   asm volatile("cp.async.wait_group 0;" ::: "memory");
        __syncthreads();

        const uint32_t sa = sbase + (uint32_t)(kt & 3) * STAGEB;
        const uint32_t sb = sa + ABYTES;

#pragma unroll
        for (int ks = 0; ks < 2; ++ks) {               // two k16 steps per BK=32
            uint32_t a[4][4], b[4][2];
#pragma unroll
            for (int mi = 0; mi < 4; ++mi) {
                const uint32_t addr = sa +
                    ((uint32_t)(wm * 64 + mi * 16) + a_row) * (ASTR * 2) +
                    ((uint32_t)(ks * 16) + a_colk) * 2;
                asm volatile(
                    "ldmatrix.sync.aligned.m8n8.x4.shared.b16 {%0,%1,%2,%3}, [%4];"
                    : "=r"(a[mi][0]), "=r"(a[mi][1]), "=r"(a[mi][2]), "=r"(a[mi][3])
                    : "r"(addr));
            }
#pragma unroll
            for (int njp = 0; njp < 2; ++njp) {        // each x4.trans covers 2 nj
                const uint32_t addr = sb +
                    ((uint32_t)(ks * 16) + b_krow) * (BSTR * 2) +
                    ((uint32_t)(wn * 32 + njp * 16) + b_coln) * 2;
                asm volatile(
                    "ldmatrix.sync.aligned.m8n8.x4.trans.shared.b16 {%0,%1,%2,%3}, [%4];"
                    : "=r"(b[njp * 2][0]), "=r"(b[njp * 2][1]),
                      "=r"(b[njp * 2 + 1][0]), "=r"(b[njp * 2 + 1][1])
                    : "r"(addr));
            }
#pragma unroll
            for (int mi = 0; mi < 4; ++mi)
#pragma unroll
                for (int nj = 0; nj < 4; ++nj)
                    asm volatile(
                        "mma.sync.aligned.m16n8k16.row.col.f32.f16.f16.f32 "
                        "{%0,%1,%2,%3}, {%4,%5,%6,%7}, {%8,%9}, {%0,%1,%2,%3};"
                        : "+f"(acc[mi][nj][0]), "+f"(acc[mi][nj][1]),
                          "+f"(acc[mi][nj][2]), "+f"(acc[mi][nj][3])
                        : "r"(a[mi][0]), "r"(a[mi][1]), "r"(a[mi][2]), "r"(a[mi][3]),
                          "r"(b[nj][0]), "r"(b[nj][1]));
        }
        if (kt + 3 < nk) load_stage(kt + 3, (kt + 3) & 3);
    }

    // epilogue: c0,c1 at (row g, cols 2tig,2tig+1); c2,c3 at row g+8
#pragma unroll
    for (int mi = 0; mi < 4; ++mi) {
        const int r0 = bm + wm * 64 + mi * 16 + g;
#pragma unroll
        for (int nj = 0; nj < 4; ++nj) {
            const int c0 = bn + wn * 32 + nj * 8 + tig * 2;
            float bx = 0.f, by = 0.f;
            if (bias) { bx = bias[c0]; by = bias[c0 + 1]; }
            float v0 = acc[mi][nj][0] + bx, v1 = acc[mi][nj][1] + by;
            float v2 = acc[mi][nj][2] + bx, v3 = acc[mi][nj][3] + by;
            if (RELU) {
                v0 = fmaxf(v0, 0.f); v1 = fmaxf(v1, 0.f);
                v2 = fmaxf(v2, 0.f); v3 = fmaxf(v3, 0.f);
            }
            if (OUTH) {
                __half* Ch = (__half*)Cv;
                *(__half2*)(Ch + (size_t)r0 * N + c0)       = __floats2half2_rn(v0, v1);
                *(__half2*)(Ch + (size_t)(r0 + 8) * N + c0) = __floats2half2_rn(v2, v3);
            } else {
                *(float2*)(Cf + (size_t)r0 * N + c0)       = make_float2(v0, v1);
                *(float2*)(Cf + (size_t)(r0 + 8) * N + c0) = make_float2(v2, v3);
            }
        }
    }
}

// ---------------------------------------------------------------------------
// out[i] = half(in[i])  (8 floats per thread)
// ---------------------------------------------------------------------------
__global__ void f2h_kernel(const float* __restrict__ in, __half* __restrict__ out) {
    const int i = blockIdx.x * blockDim.x + threadIdx.x;
    float4 v0 = ((const float4*)in)[2 * i];
    float4 v1 = ((const float4*)in)[2 * i + 1];
    __half2 h0 = __floats2half2_rn(v0.x, v0.y);
    __half2 h1 = __floats2half2_rn(v0.z, v0.w);
    __half2 h2 = __floats2half2_rn(v1.x, v1.y);
    __half2 h3 = __floats2half2_rn(v1.z, v1.w);
    __half2* o = (__half2*)out + 4 * i;
    o[0] = h0; o[1] = h1; o[2] = h2; o[3] = h3;
}

// ---------------------------------------------------------------------------
// c[i] = half(p0[i]+p1[i]+p2[i]+p3[i])  (split-K=4 combine for Wvo)
// ---------------------------------------------------------------------------
__global__ void comb4h_kernel(const float* __restrict__ p, __half* __restrict__ c) {
    const int i = blockIdx.x * blockDim.x + threadIdx.x;
    const size_t st = (size_t)DM * DM / 4;     // in float4 units
    float4 v0 = ((const float4*)p)[i];
    float4 v1 = ((const float4*)p)[i + st];
    float4 v2 = ((const float4*)p)[i + 2 * st];
    float4 v3 = ((const float4*)p)[i + 3 * st];
    float a = (v0.x + v1.x) + (v2.x + v3.x);
    float b = (v0.y + v1.y) + (v2.y + v3.y);
    float d = (v0.z + v1.z) + (v2.z + v3.z);
    float e = (v0.w + v1.w) + (v2.w + v3.w);
    ((__half2*)c)[2 * i]     = __floats2half2_rn(a, b);
    ((__half2*)c)[2 * i + 1] = __floats2half2_rn(d, e);
}

// ---------------------------------------------------------------------------
// bvo = bv @ Wo + bo, two-stage k-split (deterministic, f32)
// ---------------------------------------------------------------------------
__global__ void bvo_part_kernel(const float* __restrict__ bv, const float* __restrict__ Wo,
                                float* __restrict__ part) {
    const int n = blockIdx.x * 128 + threadIdx.x;
    const int kc = blockIdx.y;
    float s = 0.f;
#pragma unroll 4
    for (int k = kc * 128; k < kc * 128 + 128; ++k)
        s += bv[k] * Wo[(size_t)k * DM + n];
    part[kc * DM + n] = s;
}
__global__ void bvo_comb_kernel(const float* __restrict__ part, const float* __restrict__ bo,
                                float* __restrict__ bvo) {
    const int n = blockIdx.x * 256 + threadIdx.x;
    float s = bo[n];
#pragma unroll
    for (int j = 0; j < 8; ++j) s += part[j * DM + n];
    bvo[n] = s;
}

// ---------------------------------------------------------------------------
// out[row] = LayerNorm(res[row] + add[row]) * gamma + beta (f32),
// optional half copy for downstream GEMM A operand.
// ---------------------------------------------------------------------------
__global__ __launch_bounds__(256)
void add_ln_kernel(const float* __restrict__ res, const float* __restrict__ add,
                   const float* __restrict__ gamma, const float* __restrict__ beta,
                   float* __restrict__ out, __half* __restrict__ out_h) {
    const int row = blockIdx.x;
    const int t = threadIdx.x;
    const float4 r = ((const float4*)(res + (size_t)row * DM))[t];
    const float4 a = ((const float4*)(add + (size_t)row * DM))[t];
    float v0 = r.x + a.x, v1 = r.y + a.y, v2 = r.z + a.z, v3 = r.w + a.w;

    float s  = v0 + v1 + v2 + v3;
    float ss = v0 * v0 + v1 * v1 + v2 * v2 + v3 * v3;
#pragma unroll
    for (int o = 16; o > 0; o >>= 1) {
        s  += __shfl_xor_sync(0xFFFFFFFFu, s, o);
        ss += __shfl_xor_sync(0xFFFFFFFFu, ss, o);
    }
    __shared__ float sh_s[8], sh_ss[8];
    const int w = t >> 5, l = t & 31;
    if (l == 0) { sh_s[w] = s; sh_ss[w] = ss; }
    __syncthreads();
    if (w == 0) {
        s  = (l < 8) ? sh_s[l]  : 0.f;
        ss = (l < 8) ? sh_ss[l] : 0.f;
#pragma unroll
        for (int o = 4; o > 0; o >>= 1) {
            s  += __shfl_xor_sync(0xFFFFFFFFu, s, o);
            ss += __shfl_xor_sync(0xFFFFFFFFu, ss, o);
        }
        if (l == 0) { sh_s[0] = s; sh_ss[0] = ss; }
    }
    __syncthreads();
    const float mean = sh_s[0] * (1.f / DM);
    const float var  = sh_ss[0] * (1.f / DM) - mean * mean;
    const float inv  = rsqrtf(var + EPS);

    const float4 gg = ((const float4*)gamma)[t];
    const float4 bb = ((const float4*)beta)[t];
    float4 o4;
    o4.x = (v0 - mean) * inv * gg.x + bb.x;
    o4.y = (v1 - mean) * inv * gg.y + bb.y;
    o4.z = (v2 - mean) * inv * gg.z + bb.z;
    o4.w = (v3 - mean) * inv * gg.w + bb.w;
    ((float4*)(out + (size_t)row * DM))[t] = o4;
    if (out_h) {
        __half2* oh = (__half2*)(out_h + (size_t)row * DM);
        oh[2 * t]     = __floats2half2_rn(o4.x, o4.y);
        oh[2 * t + 1] = __floats2half2_rn(o4.z, o4.w);
    }
}

// ---------------------------------------------------------------------------
// Launch. Diagonal-only mask => attention == V projection. Layer reduces to:
//   attn = x @ (Wv@Wo) + (bv@Wo + bo)
//   h    = LN(x + attn; g1, beta1)
//   out  = LN(h + relu(h@W1+b1)@W2 + b2; g2, beta2)
// Preprocessing (f2h conversions, bvo) runs on forked side streams so it
// overlaps the fold/attn GEMM chain (standard fork-join capture pattern).
// ---------------------------------------------------------------------------
extern "C" void kernel_launch(void* const* d_in, const int* in_sizes, int n_in,
                              void* d_out, int out_size) {
    const float* x   = (const float*)d_in[0];
    const float* Wv  = (const float*)d_in[6];
    const float* bv  = (const float*)d_in[7];
    const float* Wo  = (const float*)d_in[8];
    const float* bo  = (const float*)d_in[9];
    const float* W1  = (const float*)d_in[10];
    const float* b1  = (const float*)d_in[11];
    const float* W2  = (const float*)d_in[12];
    const float* b2  = (const float*)d_in[13];
    const float* g1  = (const float*)d_in[14];
    const float* be1 = (const float*)d_in[15];
    const float* g2  = (const float*)d_in[16];
    const float* be2 = (const float*)d_in[17];
    float* out = (float*)d_out;

    __half *xh, *Wvh, *Woh, *W1h, *W2h, *Wvoh, *hh, *ffh;
    float *bvo, *bvop, *attn, *h, *ff2;
    cudaGetSymbolAddress((void**)&xh,   g_xh);
    cudaGetSymbolAddress((void**)&Wvh,  g_Wvh);
    cudaGetSymbolAddress((void**)&Woh,  g_Woh);
    cudaGetSymbolAddress((void**)&W1h,  g_W1h);
    cudaGetSymbolAddress((void**)&W2h,  g_W2h);
    cudaGetSymbolAddress((void**)&Wvoh, g_Wvoh);
    cudaGetSymbolAddress((void**)&hh,   g_hh);
    cudaGetSymbolAddress((void**)&ffh,  g_ffh);
    cudaGetSymbolAddress((void**)&bvo,  g_bvo);
    cudaGetSymbolAddress((void**)&bvop, g_bvop);
    cudaGetSymbolAddress((void**)&attn, g_attn);
    cudaGetSymbolAddress((void**)&h,    g_h);
    cudaGetSymbolAddress((void**)&ff2,  g_ff2);

    static bool init_done = false;
    static cudaStream_t s1, s2, s3;
    static cudaEvent_t ev_root, ev_x, ev_w12, ev_bvo;
    if (!init_done) {
        cudaFuncSetAttribute(hgemm<0, 1, 0>, cudaFuncAttributeMaxDynamicSharedMemorySize, SMEM_TOTAL);
        cudaFuncSetAttribute(hgemm<1, 1, 1>, cudaFuncAttributeMaxDynamicSharedMemorySize, SMEM_TOTAL);
        cudaFuncSetAttribute(hgemm<0, 4, 0>, cudaFuncAttributeMaxDynamicSharedMemorySize, SMEM_TOTAL);
        cudaStreamCreateWithFlags(&s1, cudaStreamNonBlocking);
        cudaStreamCreateWithFlags(&s2, cudaStreamNonBlocking);
        cudaStreamCreateWithFlags(&s3, cudaStreamNonBlocking);
        cudaEventCreateWithFlags(&ev_root, cudaEventDisableTiming);
        cudaEventCreateWithFlags(&ev_x,    cudaEventDisableTiming);
        cudaEventCreateWithFlags(&ev_w12,  cudaEventDisableTiming);
        cudaEventCreateWithFlags(&ev_bvo,  cudaEventDisableTiming);
        init_done = true;
    }

    // fork side streams off the main (capture) stream
    cudaEventRecord(ev_root, 0);
    cudaStreamWaitEvent(s1, ev_root, 0);
    cudaStreamWaitEvent(s2, ev_root, 0);
    cudaStreamWaitEvent(s3, ev_root, 0);

    // side 1: x conversion (needed by attn GEMM)
    f2h_kernel<<<(MROWS * DM / 8) / 256, 256, 0, s1>>>(x, xh);
    cudaEventRecord(ev_x, s1);

    // side 2: FFN weight conversions (needed by FFN1/FFN2)
    f2h_kernel<<<(DM * FF / 8) / 256, 256, 0, s2>>>(W1, W1h);
    f2h_kernel<<<(FF * DM / 8) / 256, 256, 0, s2>>>(W2, W2h);
    cudaEventRecord(ev_w12, s2);

    // side 3: bvo = bv @ Wo + bo (needed by attn GEMM)
    bvo_part_kernel<<<dim3(DM / 128, 8), 128, 0, s3>>>(bv, Wo, bvop);
    bvo_comb_kernel<<<DM / 256, 256, 0, s3>>>(bvop, bo, bvo);
    cudaEventRecord(ev_bvo, s3);

    // main: Wv/Wo conversion, then Wvoh = half(Wv @ Wo) via split-K=4
    f2h_kernel<<<(DM * DM / 8) / 256, 256>>>(Wv, Wvh);
    f2h_kernel<<<(DM * DM / 8) / 256, 256>>>(Wo, Woh);
    hgemm<0, 4, 0><<<dim3(DM / 128, DM / 128, 4), 256, SMEM_TOTAL>>>(
        Wvh, Woh, nullptr, attn, DM, DM, DM);
    comb4h_kernel<<<(DM * DM / 4) / 256, 256>>>(attn, Wvoh);

    // join x + bvo, then attn = xh @ Wvoh + bvo
    cudaStreamWaitEvent(0, ev_x, 0);
    cudaStreamWaitEvent(0, ev_bvo, 0);
    hgemm<0, 1, 0><<<dim3(DM / 128, MROWS / 128), 256, SMEM_TOTAL>>>(
        xh, Wvoh, bvo, attn, MROWS, DM, DM);

    // h = LN(x + attn); hh = half(h)
    add_ln_kernel<<<MROWS, 256>>>(x, attn, g1, be1, h, hh);

    // join W1/W2, then FFN
    cudaStreamWaitEvent(0, ev_w12, 0);
    hgemm<1, 1, 1><<<dim3(FF / 128, MROWS / 128), 256, SMEM_TOTAL>>>(
        hh, W1h, b1, ffh, MROWS, FF, DM);
    hgemm<0, 1, 0><<<dim3(DM / 128, MROWS / 128), 256, SMEM_TOTAL>>>(
        ffh, W2h, b2, ff2, MROWS, DM, FF);

    // out = LN(h + ff2)
    add_ln_kernel<<<MROWS, 256>>>(h, ff2, g2, be2, out, nullptr);
}

// round 11
// speedup vs baseline: 1.2141x; 1.0361x over previous
#include <cuda_runtime.h>
#include <cuda_fp16.h>
#include <cstdint>
#include <cstddef>

// Problem constants
#define DM 1024
#define FF 4096
#define MROWS 4096          // B*S = 2*2048
#define HROWS 2048          // rows per half-pipeline
#define EPS 1e-5f

// ---------------------------------------------------------------------------
// Scratch (static device globals; no runtime allocation)
// ---------------------------------------------------------------------------
__device__ __half g_xh[MROWS * DM];     // half(x)               (8 MB)
__device__ __half g_Wvh[DM * DM];       // half(Wv)              (2 MB)
__device__ __half g_Woh[DM * DM];       // half(Wo)              (2 MB)
__device__ __half g_W1h[DM * FF];       // half(W1)              (8 MB)
__device__ __half g_W2h[FF * DM];       // half(W2)              (8 MB)
__device__ __half g_Wvoh[DM * DM];      // half(Wv@Wo)           (2 MB)
__device__ float  g_bvo[DM];            // bv @ Wo + bo
__device__ float  g_bvop[64 * DM];      // bvo k-split partials
__device__ float  g_attn[4 * DM * DM];  // fold split-K partials, then x@Wvo+bvo (16 MB)
__device__ float  g_h[MROWS * DM];      // LN1 output (f32)      (16 MB)
__device__ __half g_hh[MROWS * DM];     // LN1 output (half)     (8 MB)
__device__ __half g_ffh[MROWS * FF];    // relu(h@W1+b1) half    (32 MB)
__device__ float  g_ff2[MROWS * DM];    // ff@W2+b2              (16 MB)

// ---------------------------------------------------------------------------
// helpers
// ---------------------------------------------------------------------------
__device__ __forceinline__ uint32_t smem_u32(const void* p) {
    uint32_t a;
    asm("{ .reg .u64 t; cvta.to.shared.u64 t, %1; cvt.u32.u64 %0, t; }"
        : "=r"(a) : "l"(p));
    return a;
}

__device__ __forceinline__ void cp16(uint32_t s, const void* g) {
    asm volatile("cp.async.cg.shared.global [%0], [%1], 16;" :: "r"(s), "l"(g) : "memory");
}

// SMEM geometry (halfs). Padding keeps ldmatrix conflict-free.
#define ASTR 40
#define BSTR 136
#define ABYTES (128 * ASTR * 2)             // 10240
#define BBYTES (32 * BSTR * 2)              // 8704
#define STAGEB (ABYTES + BBYTES)            // 18944
#define NSTAGE 4
#define SMEM_TOTAL (NSTAGE * STAGEB)        // 75776  (x2 CTAs/SM = 151552)

// ---------------------------------------------------------------------------
// fp16 mma.sync GEMM: C[M,N] = A[M,K] @ B[K,N] (+ bias[N]) (+ReLU)
// Tile 128x128, BK=32. 256 threads = 8 warps (2 M x 4 N), warp tile 64x32.
// 4-stage cp.async pipeline (3 in flight), 2 CTAs/SM.
// NSPLIT>1: blockIdx.z selects K-chunk and a distinct f32 output buffer.
// ---------------------------------------------------------------------------
template <int RELU, int NSPLIT, int OUTH>
__global__ __launch_bounds__(256, 2)
void hgemm(const __half* __restrict__ A, const __half* __restrict__ B,
           const float* __restrict__ bias, void* __restrict__ Cv,
           int M, int N, int K) {
    extern __shared__ __align__(16) char smem_raw[];
    const uint32_t sbase = smem_u32(smem_raw);

    int k0g = 0, klen = K;
    float* Cf = (float*)Cv;
    if (NSPLIT > 1) {
        klen = K / NSPLIT;
        k0g = blockIdx.z * klen;
        Cf += (size_t)blockIdx.z * M * N;
    }

    const int tid  = threadIdx.x;
    const int wid  = tid >> 5, lane = tid & 31;
    const int g    = lane >> 2, tig = lane & 3;
    const int wm   = wid >> 2, wn = wid & 3;        // 2 x 4 warp grid
    const int bm   = blockIdx.y * 128, bn = blockIdx.x * 128;
    const int nk   = klen >> 5;

    auto load_stage = [&](int kt, int st) {
        const uint32_t sa = sbase + (uint32_t)st * STAGEB;
        const uint32_t sb = sa + ABYTES;
        const int kk = k0g + (kt << 5);
#pragma unroll
        for (int i = 0; i < 2; ++i) {
            int c = tid + i * 256;
            int r = c >> 2, s = c & 3;
            cp16(sa + (uint32_t)(r * (ASTR * 2) + s * 16),
                 A + (size_t)(bm + r) * K + kk + s * 8);
        }
#pragma unroll
        for (int i = 0; i < 2; ++i) {
            int c = tid + i * 256;
            int r = c >> 4, s = c & 15;
            cp16(sb + (uint32_t)(r * (BSTR * 2) + s * 16),
                 B + (size_t)(kk + r) * N + bn + s * 8);
        }
        asm volatile("cp.async.commit_group;" ::: "memory");
    };

    const uint32_t a_row  = (uint32_t)(lane & 15);
    const uint32_t a_colk = (uint32_t)((lane >> 4) * 8);
    const uint32_t b_krow = (uint32_t)(lane & 15);
    const uint32_t b_coln = (uint32_t)((lane >> 4) * 8);

    float acc[4][4][4];
#pragma unroll
    for (int i = 0; i < 4; ++i)
#pragma unroll
        for (int j = 0; j < 4; ++j)
#pragma unroll
            for (int q = 0; q < 4; ++q) acc[i][j][q] = 0.f;

    load_stage(0, 0);
    load_stage(1, 1);
    load_stage(2, 2);

    for (int kt = 0; kt < nk; ++kt) {
        if (kt < nk - 2)       asm volatile("cp.async.wait_group 2;" ::: "memory");
        else if (kt == nk - 2) asm volatile("cp.async.wait_group 1;" ::: "memory");
        else                   asm volatile("cp.async.wait_group 0;" ::: "memory");
        __syncthreads();

        const uint32_t sa = sbase + (uint32_t)(kt & 3) * STAGEB;
        const uint32_t sb = sa + ABYTES;

#pragma unroll
        for (int ks = 0; ks < 2; ++ks) {               // two k16 steps per BK=32
            uint32_t a[4][4], b[4][2];
#pragma unroll
            for (int mi = 0; mi < 4; ++mi) {
                const uint32_t addr = sa +
                    ((uint32_t)(wm * 64 + mi * 16) + a_row) * (ASTR * 2) +
                    ((uint32_t)(ks * 16) + a_colk) * 2;
                asm volatile(
                    "ldmatrix.sync.aligned.m8n8.x4.shared.b16 {%0,%1,%2,%3}, [%4];"
                    : "=r"(a[mi][0]), "=r"(a[mi][1]), "=r"(a[mi][2]), "=r"(a[mi][3])
                    : "r"(addr));
            }
#pragma unroll
            for (int njp = 0; njp < 2; ++njp) {        // each x4.trans covers 2 nj
                const uint32_t addr = sb +
                    ((uint32_t)(ks * 16) + b_krow) * (BSTR * 2) +
                    ((uint32_t)(wn * 32 + njp * 16) + b_coln) * 2;
                asm volatile(
                    "ldmatrix.sync.aligned.m8n8.x4.trans.shared.b16 {%0,%1,%2,%3}, [%4];"
                    : "=r"(b[njp * 2][0]), "=r"(b[njp * 2][1]),
                      "=r"(b[njp * 2 + 1][0]), "=r"(b[njp * 2 + 1][1])
                    : "r"(addr));
            }
#pragma unroll
            for (int mi = 0; mi < 4; ++mi)
#pragma unroll
                for (int nj = 0; nj < 4; ++nj)
                    asm volatile(
                        "mma.sync.aligned.m16n8k16.row.col.f32.f16.f16.f32 "
                        "{%0,%1,%2,%3}, {%4,%5,%6,%7}, {%8,%9}, {%0,%1,%2,%3};"
                        : "+f"(acc[mi][nj][0]), "+f"(acc[mi][nj][1]),
                          "+f"(acc[mi][nj][2]), "+f"(acc[mi][nj][3])
                        : "r"(a[mi][0]), "r"(a[mi][1]), "r"(a[mi][2]), "r"(a[mi][3]),
                          "r"(b[nj][0]), "r"(b[nj][1]));
        }
        if (kt + 3 < nk) load_stage(kt + 3, (kt + 3) & 3);
    }

    // epilogue
#pragma unroll
    for (int mi = 0; mi < 4; ++mi) {
        const int r0 = bm + wm * 64 + mi * 16 + g;
#pragma unroll
        for (int nj = 0; nj < 4; ++nj) {
            const int c0 = bn + wn * 32 + nj * 8 + tig * 2;
            float bx = 0.f, by = 0.f;
            if (bias) { bx = bias[c0]; by = bias[c0 + 1]; }
            float v0 = acc[mi][nj][0] + bx, v1 = acc[mi][nj][1] + by;
            float v2 = acc[mi][nj][2] + bx, v3 = acc[mi][nj][3] + by;
            if (RELU) {
                v0 = fmaxf(v0, 0.f); v1 = fmaxf(v1, 0.f);
                v2 = fmaxf(v2, 0.f); v3 = fmaxf(v3, 0.f);
            }
            if (OUTH) {
                __half* Ch = (__half*)Cv;
                *(__half2*)(Ch + (size_t)r0 * N + c0)       = __floats2half2_rn(v0, v1);
                *(__half2*)(Ch + (size_t)(r0 + 8) * N + c0) = __floats2half2_rn(v2, v3);
            } else {
                *(float2*)(Cf + (size_t)r0 * N + c0)       = make_float2(v0, v1);
                *(float2*)(Cf + (size_t)(r0 + 8) * N + c0) = make_float2(v2, v3);
            }
        }
    }
}

// ---------------------------------------------------------------------------
// out[i] = half(in[i])  (8 floats per thread)
// ---------------------------------------------------------------------------
__global__ void f2h_kernel(const float* __restrict__ in, __half* __restrict__ out) {
    const int i = blockIdx.x * blockDim.x + threadIdx.x;
    float4 v0 = ((const float4*)in)[2 * i];
    float4 v1 = ((const float4*)in)[2 * i + 1];
    __half2 h0 = __floats2half2_rn(v0.x, v0.y);
    __half2 h1 = __floats2half2_rn(v0.z, v0.w);
    __half2 h2 = __floats2half2_rn(v1.x, v1.y);
    __half2 h3 = __floats2half2_rn(v1.z, v1.w);
    __half2* o = (__half2*)out + 4 * i;
    o[0] = h0; o[1] = h1; o[2] = h2; o[3] = h3;
}

// ---------------------------------------------------------------------------
// c[i] = half(p0[i]+p1[i]+p2[i]+p3[i])  (split-K=4 combine for Wvo)
// ---------------------------------------------------------------------------
__global__ void comb4h_kernel(const float* __restrict__ p, __half* __restrict__ c) {
    const int i = blockIdx.x * blockDim.x + threadIdx.x;
    const size_t st = (size_t)DM * DM / 4;     // in float4 units
    float4 v0 = ((const float4*)p)[i];
    float4 v1 = ((const float4*)p)[i + st];
    float4 v2 = ((const float4*)p)[i + 2 * st];
    float4 v3 = ((const float4*)p)[i + 3 * st];
    float a = (v0.x + v1.x) + (v2.x + v3.x);
    float b = (v0.y + v1.y) + (v2.y + v3.y);
    float d = (v0.z + v1.z) + (v2.z + v3.z);
    float e = (v0.w + v1.w) + (v2.w + v3.w);
    ((__half2*)c)[2 * i]     = __floats2half2_rn(a, b);
    ((__half2*)c)[2 * i + 1] = __floats2half2_rn(d, e);
}

// ---------------------------------------------------------------------------
// bvo = bv @ Wo + bo, 64-way k-split (deterministic, f32)
// ---------------------------------------------------------------------------
__global__ void bvo_part_kernel(const float* __restrict__ bv, const float* __restrict__ Wo,
                                float* __restrict__ part) {
    const int n = blockIdx.x * 128 + threadIdx.x;
    const int kc = blockIdx.y;
    float s = 0.f;
#pragma unroll
    for (int k = kc * 16; k < kc * 16 + 16; ++k)
        s += bv[k] * Wo[(size_t)k * DM + n];
    part[kc * DM + n] = s;
}
__global__ void bvo_comb_kernel(const float* __restrict__ part, const float* __restrict__ bo,
                                float* __restrict__ bvo) {
    const int n = blockIdx.x * 256 + threadIdx.x;
    float s = bo[n];
#pragma unroll
    for (int j = 0; j < 64; ++j) s += part[j * DM + n];
    bvo[n] = s;
}

// ---------------------------------------------------------------------------
// out[row] = LayerNorm(res[row] + add[row]) * gamma + beta (f32),
// optional half copy for downstream GEMM A operand.
// ---------------------------------------------------------------------------
__global__ __launch_bounds__(256)
void add_ln_kernel(const float* __restrict__ res, const float* __restrict__ add,
                   const float* __restrict__ gamma, const float* __restrict__ beta,
                   float* __restrict__ out, __half* __restrict__ out_h) {
    const int row = blockIdx.x;
    const int t = threadIdx.x;
    const float4 r = ((const float4*)(res + (size_t)row * DM))[t];
    const float4 a = ((const float4*)(add + (size_t)row * DM))[t];
    float v0 = r.x + a.x, v1 = r.y + a.y, v2 = r.z + a.z, v3 = r.w + a.w;

    float s  = v0 + v1 + v2 + v3;
    float ss = v0 * v0 + v1 * v1 + v2 * v2 + v3 * v3;
#pragma unroll
    for (int o = 16; o > 0; o >>= 1) {
        s  += __shfl_xor_sync(0xFFFFFFFFu, s, o);
        ss += __shfl_xor_sync(0xFFFFFFFFu, ss, o);
    }
    __shared__ float sh_s[8], sh_ss[8];
    const int w = t >> 5, l = t & 31;
    if (l == 0) { sh_s[w] = s; sh_ss[w] = ss; }
    __syncthreads();
    if (w == 0) {
        s  = (l < 8) ? sh_s[l]  : 0.f;
        ss = (l < 8) ? sh_ss[l] : 0.f;
#pragma unroll
        for (int o = 4; o > 0; o >>= 1) {
            s  += __shfl_xor_sync(0xFFFFFFFFu, s, o);
            ss += __shfl_xor_sync(0xFFFFFFFFu, ss, o);
        }
        if (l == 0) { sh_s[0] = s; sh_ss[0] = ss; }
    }
    __syncthreads();
    const float mean = sh_s[0] * (1.f / DM);
    const float var  = sh_ss[0] * (1.f / DM) - mean * mean;
    const float inv  = rsqrtf(var + EPS);

    const float4 gg = ((const float4*)gamma)[t];
    const float4 bb = ((const float4*)beta)[t];
    float4 o4;
    o4.x = (v0 - mean) * inv * gg.x + bb.x;
    o4.y = (v1 - mean) * inv * gg.y + bb.y;
    o4.z = (v2 - mean) * inv * gg.z + bb.z;
    o4.w = (v3 - mean) * inv * gg.w + bb.w;
    ((float4*)(out + (size_t)row * DM))[t] = o4;
    if (out_h) {
        __half2* oh = (__half2*)(out_h + (size_t)row * DM);
        oh[2 * t]     = __floats2half2_rn(o4.x, o4.y);
        oh[2 * t + 1] = __floats2half2_rn(o4.z, o4.w);
    }
}

// ---------------------------------------------------------------------------
// Launch. Diagonal-only mask => attention == V projection. Layer reduces to:
//   attn = x @ (Wv@Wo) + (bv@Wo + bo)
//   h    = LN(x + attn; g1, beta1)
//   out  = LN(h + relu(h@W1+b1)@W2 + b2; g2, beta2)
// Post-fold computation is row-independent; it runs as 2 half-row pipelines
// (main stream + s1) to eliminate per-stage wave quantization, with weight
// conversion (s2) and bvo (s3) forked off the root. 3 side streams total —
// the same inventory R9 ran with a clean allocation checkpoint.
// ---------------------------------------------------------------------------
extern "C" void kernel_launch(void* const* d_in, const int* in_sizes, int n_in,
                              void* d_out, int out_size) {
    const float* x   = (const float*)d_in[0];
    const float* Wv  = (const float*)d_in[6];
    const float* bv  = (const float*)d_in[7];
    const float* Wo  = (const float*)d_in[8];
    const float* bo  = (const float*)d_in[9];
    const float* W1  = (const float*)d_in[10];
    const float* b1  = (const float*)d_in[11];
    const float* W2  = (const float*)d_in[12];
    const float* b2  = (const float*)d_in[13];
    const float* g1  = (const float*)d_in[14];
    const float* be1 = (const float*)d_in[15];
    const float* g2  = (const float*)d_in[16];
    const float* be2 = (const float*)d_in[17];
    float* out = (float*)d_out;

    __half *xh, *Wvh, *Woh, *W1h, *W2h, *Wvoh, *hh, *ffh;
    float *bvo, *bvop, *attn, *h, *ff2;
    cudaGetSymbolAddress((void**)&xh,   g_xh);
    cudaGetSymbolAddress((void**)&Wvh,  g_Wvh);
    cudaGetSymbolAddress((void**)&Woh,  g_Woh);
    cudaGetSymbolAddress((void**)&W1h,  g_W1h);
    cudaGetSymbolAddress((void**)&W2h,  g_W2h);
    cudaGetSymbolAddress((void**)&Wvoh, g_Wvoh);
    cudaGetSymbolAddress((void**)&hh,   g_hh);
    cudaGetSymbolAddress((void**)&ffh,  g_ffh);
    cudaGetSymbolAddress((void**)&bvo,  g_bvo);
    cudaGetSymbolAddress((void**)&bvop, g_bvop);
    cudaGetSymbolAddress((void**)&attn, g_attn);
    cudaGetSymbolAddress((void**)&h,    g_h);
    cudaGetSymbolAddress((void**)&ff2,  g_ff2);

    static bool init_done = false;
    static cudaStream_t s1, s2, s3;
    static cudaEvent_t ev_root, ev_x, ev_w12, ev_bvo, ev_wvo, ev_h1;
    if (!init_done) {
        cudaFuncSetAttribute(hgemm<0, 1, 0>, cudaFuncAttributeMaxDynamicSharedMemorySize, SMEM_TOTAL);
        cudaFuncSetAttribute(hgemm<1, 1, 1>, cudaFuncAttributeMaxDynamicSharedMemorySize, SMEM_TOTAL);
        cudaFuncSetAttribute(hgemm<0, 4, 0>, cudaFuncAttributeMaxDynamicSharedMemorySize, SMEM_TOTAL);
        cudaStreamCreateWithFlags(&s1, cudaStreamNonBlocking);
        cudaStreamCreateWithFlags(&s2, cudaStreamNonBlocking);
        cudaStreamCreateWithFlags(&s3, cudaStreamNonBlocking);
        cudaEventCreateWithFlags(&ev_root, cudaEventDisableTiming);
        cudaEventCreateWithFlags(&ev_x,    cudaEventDisableTiming);
        cudaEventCreateWithFlags(&ev_w12,  cudaEventDisableTiming);
        cudaEventCreateWithFlags(&ev_bvo,  cudaEventDisableTiming);
        cudaEventCreateWithFlags(&ev_wvo,  cudaEventDisableTiming);
        cudaEventCreateWithFlags(&ev_h1,   cudaEventDisableTiming);
        init_done = true;
    }

    const size_t rd = (size_t)HROWS * DM;   // half offset in DM-wide tensors
    const size_t rf = (size_t)HROWS * FF;   // half offset in FF-wide tensors

    // ---- fork ----
    cudaEventRecord(ev_root, 0);
    cudaStreamWaitEvent(s1, ev_root, 0);
    cudaStreamWaitEvent(s2, ev_root, 0);
    cudaStreamWaitEvent(s3, ev_root, 0);

    // s2: FFN weight conversions (needed by FFN1/FFN2)
    f2h_kernel<<<(DM * FF / 8) / 256, 256, 0, s2>>>(W1, W1h);
    f2h_kernel<<<(FF * DM / 8) / 256, 256, 0, s2>>>(W2, W2h);
    cudaEventRecord(ev_w12, s2);

    // s3: bvo = bv @ Wo + bo (64-way k-split, ~3us)
    bvo_part_kernel<<<dim3(DM / 128, 64), 128, 0, s3>>>(bv, Wo, bvop);
    bvo_comb_kernel<<<DM / 256, 256, 0, s3>>>(bvop, bo, bvo);
    cudaEventRecord(ev_bvo, s3);

    // s1: full x conversion (overlaps fold), then half-1 pipeline
    f2h_kernel<<<(MROWS * DM / 8) / 256, 256, 0, s1>>>(x, xh);
    cudaEventRecord(ev_x, s1);

    // main: Wv/Wo conversion, Wvoh = half(Wv @ Wo) via split-K=4 (scratch g_attn)
    f2h_kernel<<<(DM * DM / 8) / 256, 256>>>(Wv, Wvh);
    f2h_kernel<<<(DM * DM / 8) / 256, 256>>>(Wo, Woh);
    hgemm<0, 4, 0><<<dim3(DM / 128, DM / 128, 4), 256, SMEM_TOTAL>>>(
        Wvh, Woh, nullptr, attn, DM, DM, DM);
    comb4h_kernel<<<(DM * DM / 4) / 256, 256>>>(attn, Wvoh);
    cudaEventRecord(ev_wvo, 0);

    // ---- half-1 pipeline on s1 (rows HROWS..MROWS) ----
    cudaStreamWaitEvent(s1, ev_wvo, 0);
    cudaStreamWaitEvent(s1, ev_bvo, 0);
    hgemm<0, 1, 0><<<dim3(DM / 128, HROWS / 128), 256, SMEM_TOTAL, s1>>>(
        xh + rd, Wvoh, bvo, attn + rd, HROWS, DM, DM);
    add_ln_kernel<<<HROWS, 256, 0, s1>>>(x + rd, attn + rd, g1, be1, h + rd, hh + rd);
    cudaStreamWaitEvent(s1, ev_w12, 0);
    hgemm<1, 1, 1><<<dim3(FF / 128, HROWS / 128), 256, SMEM_TOTAL, s1>>>(
        hh + rd, W1h, b1, ffh + rf, HROWS, FF, DM);
    hgemm<0, 1, 0><<<dim3(DM / 128, HROWS / 128), 256, SMEM_TOTAL, s1>>>(
        ffh + rf, W2h, b2, ff2 + rd, HROWS, DM, FF);
    add_ln_kernel<<<HROWS, 256, 0, s1>>>(h + rd, ff2 + rd, g2, be2, out + rd, nullptr);
    cudaEventRecord(ev_h1, s1);

    // ---- half-0 pipeline on main (rows 0..HROWS) ----
    cudaStreamWaitEvent(0, ev_x, 0);
    cudaStreamWaitEvent(0, ev_bvo, 0);
    hgemm<0, 1, 0><<<dim3(DM / 128, HROWS / 128), 256, SMEM_TOTAL>>>(
        xh, Wvoh, bvo, attn, HROWS, DM, DM);
    add_ln_kernel<<<HROWS, 256>>>(x, attn, g1, be1, h, hh);
    cudaStreamWaitEvent(0, ev_w12, 0);
    hgemm<1, 1, 1><<<dim3(FF / 128, HROWS / 128), 256, SMEM_TOTAL>>>(
        hh, W1h, b1, ffh, HROWS, FF, DM);
    hgemm<0, 1, 0><<<dim3(DM / 128, HROWS / 128), 256, SMEM_TOTAL>>>(
        ffh, W2h, b2, ff2, HROWS, DM, FF);
    add_ln_kernel<<<HROWS, 256>>>(h, ff2, g2, be2, out, nullptr);

    // ---- join ----
    cudaStreamWaitEvent(0, ev_h1, 0);
}

// round 12
// speedup vs baseline: 1.2142x; 1.0001x over previous
#include <cuda_runtime.h>
#include <cuda_fp16.h>
#include <cstdint>
#include <cstddef>

// Problem constants
#define DM 1024
#define FF 4096
#define MROWS 4096          // B*S = 2*2048
#define HROWS 2048          // rows per half-pipeline
#define EPS 1e-5f

// ---------------------------------------------------------------------------
// Scratch (static device globals; no runtime allocation)
// ---------------------------------------------------------------------------
__device__ __half g_xh[MROWS * DM];     // half(x)               (8 MB)
__device__ __half g_Wvh[DM * DM];       // half(Wv)              (2 MB)
__device__ __half g_Woh[DM * DM];       // half(Wo)              (2 MB)
__device__ __half g_W1h[DM * FF];       // half(W1)              (8 MB)
__device__ __half g_W2h[FF * DM];       // half(W2)              (8 MB)
__device__ __half g_Wvoh[DM * DM];      // half(Wv@Wo)           (2 MB)
__device__ float  g_bvo[DM];            // bv @ Wo + bo
__device__ float  g_bvop[64 * DM];      // bvo k-split partials
__device__ float  g_attn[4 * DM * DM];  // fold split-K f32 partials; then attn (half view) (16 MB)
__device__ __half g_hh[MROWS * DM];     // LN1 output (half)     (8 MB)
__device__ __half g_ffh[MROWS * FF];    // relu(h@W1+b1) half    (32 MB)
__device__ __half g_ff2h[MROWS * DM];   // ff@W2+b2 (half)       (8 MB)

// ---------------------------------------------------------------------------
// helpers
// ---------------------------------------------------------------------------
__device__ __forceinline__ uint32_t smem_u32(const void* p) {
    uint32_t a;
    asm("{ .reg .u64 t; cvta.to.shared.u64 t, %1; cvt.u32.u64 %0, t; }"
        : "=r"(a) : "l"(p));
    return a;
}

__device__ __forceinline__ void cp16(uint32_t s, const void* g) {
    asm volatile("cp.async.cg.shared.global [%0], [%1], 16;" :: "r"(s), "l"(g) : "memory");
}

// SMEM geometry (halfs). Padding keeps ldmatrix conflict-free.
#define ASTR 40
#define BSTR 136
#define ABYTES (128 * ASTR * 2)             // 10240
#define BBYTES (32 * BSTR * 2)              // 8704
#define STAGEB (ABYTES + BBYTES)            // 18944
#define NSTAGE 4
#define SMEM_TOTAL (NSTAGE * STAGEB)        // 75776  (x2 CTAs/SM = 151552)

// ---------------------------------------------------------------------------
// fp16 mma.sync GEMM: C[M,N] = A[M,K] @ B[K,N] (+ bias[N]) (+ReLU)
// Tile 128x128, BK=32. 256 threads = 8 warps (2 M x 4 N), warp tile 64x32.
// 4-stage cp.async pipeline (3 in flight), 2 CTAs/SM.
// NSPLIT>1: blockIdx.z selects K-chunk and a distinct f32 output buffer.
// ---------------------------------------------------------------------------
template <int RELU, int NSPLIT, int OUTH>
__global__ __launch_bounds__(256, 2)
void hgemm(const __half* __restrict__ A, const __half* __restrict__ B,
           const float* __restrict__ bias, void* __restrict__ Cv,
           int M, int N, int K) {
    extern __shared__ __align__(16) char smem_raw[];
    const uint32_t sbase = smem_u32(smem_raw);

    int k0g = 0, klen = K;
    float* Cf = (float*)Cv;
    if (NSPLIT > 1) {
        klen = K / NSPLIT;
        k0g = blockIdx.z * klen;
        Cf += (size_t)blockIdx.z * M * N;
    }

    const int tid  = threadIdx.x;
    const int wid  = tid >> 5, lane = tid & 31;
    const int g    = lane >> 2, tig = lane & 3;
    const int wm   = wid >> 2, wn = wid & 3;        // 2 x 4 warp grid
    const int bm   = blockIdx.y * 128, bn = blockIdx.x * 128;
    const int nk   = klen >> 5;

    auto load_stage = [&](int kt, int st) {
        const uint32_t sa = sbase + (uint32_t)st * STAGEB;
        const uint32_t sb = sa + ABYTES;
        const int kk = k0g + (kt << 5);
#pragma unroll
        for (int i = 0; i < 2; ++i) {
            int c = tid + i * 256;
            int r = c >> 2, s = c & 3;
            cp16(sa + (uint32_t)(r * (ASTR * 2) + s * 16),
                 A + (size_t)(bm + r) * K + kk + s * 8);
        }
#pragma unroll
        for (int i = 0; i < 2; ++i) {
            int c = tid + i * 256;
            int r = c >> 4, s = c & 15;
            cp16(sb + (uint32_t)(r * (BSTR * 2) + s * 16),
                 B + (size_t)(kk + r) * N + bn + s * 8);
        }
        asm volatile("cp.async.commit_group;" ::: "memory");
    };

    const uint32_t a_row  = (uint32_t)(lane & 15);
    const uint32_t a_colk = (uint32_t)((lane >> 4) * 8);
    const uint32_t b_krow = (uint32_t)(lane & 15);
    const uint32_t b_coln = (uint32_t)((lane >> 4) * 8);

    float acc[4][4][4];
#pragma unroll
    for (int i = 0; i < 4; ++i)
#pragma unroll
        for (int j = 0; j < 4; ++j)
#pragma unroll
            for (int q = 0; q < 4; ++q) acc[i][j][q] = 0.f;

    load_stage(0, 0);
    load_stage(1, 1);
    load_stage(2, 2);

    for (int kt = 0; kt < nk; ++kt) {
        if (kt < nk - 2)       asm volatile("cp.async.wait_group 2;" ::: "memory");
        else if (kt == nk - 2) asm volatile("cp.async.wait_group 1;" ::: "memory");
        else                   asm volatile("cp.async.wait_group 0;" ::: "memory");
        __syncthreads();

        const uint32_t sa = sbase + (uint32_t)(kt & 3) * STAGEB;
        const uint32_t sb = sa + ABYTES;

#pragma unroll
        for (int ks = 0; ks < 2; ++ks) {               // two k16 steps per BK=32
            uint32_t a[4][4], b[4][2];
#pragma unroll
            for (int mi = 0; mi < 4; ++mi) {
                const uint32_t addr = sa +
                    ((uint32_t)(wm * 64 + mi * 16) + a_row) * (ASTR * 2) +
                    ((uint32_t)(ks * 16) + a_colk) * 2;
                asm volatile(
                    "ldmatrix.sync.aligned.m8n8.x4.shared.b16 {%0,%1,%2,%3}, [%4];"
                    : "=r"(a[mi][0]), "=r"(a[mi][1]), "=r"(a[mi][2]), "=r"(a[mi][3])
                    : "r"(addr));
            }
#pragma unroll
            for (int njp = 0; njp < 2; ++njp) {        // each x4.trans covers 2 nj
                const uint32_t addr = sb +
                    ((uint32_t)(ks * 16) + b_krow) * (BSTR * 2) +
                    ((uint32_t)(wn * 32 + njp * 16) + b_coln) * 2;
                asm volatile(
                    "ldmatrix.sync.aligned.m8n8.x4.trans.shared.b16 {%0,%1,%2,%3}, [%4];"
                    : "=r"(b[njp * 2][0]), "=r"(b[njp * 2][1]),
                      "=r"(b[njp * 2 + 1][0]), "=r"(b[njp * 2 + 1][1])
                    : "r"(addr));
            }
#pragma unroll
            for (int mi = 0; mi < 4; ++mi)
#pragma unroll
                for (int nj = 0; nj < 4; ++nj)
                    asm volatile(
                        "mma.sync.aligned.m16n8k16.row.col.f32.f16.f16.f32 "
                        "{%0,%1,%2,%3}, {%4,%5,%6,%7}, {%8,%9}, {%0,%1,%2,%3};"
                        : "+f"(acc[mi][nj][0]), "+f"(acc[mi][nj][1]),
                          "+f"(acc[mi][nj][2]), "+f"(acc[mi][nj][3])
                        : "r"(a[mi][0]), "r"(a[mi][1]), "r"(a[mi][2]), "r"(a[mi][3]),
                          "r"(b[nj][0]), "r"(b[nj][1]));
        }
        if (kt + 3 < nk) load_stage(kt + 3, (kt + 3) & 3);
    }

    // epilogue
#pragma unroll
    for (int mi = 0; mi < 4; ++mi) {
        const int r0 = bm + wm * 64 + mi * 16 + g;
#pragma unroll
        for (int nj = 0; nj < 4; ++nj) {
            const int c0 = bn + wn * 32 + nj * 8 + tig * 2;
            float bx = 0.f, by = 0.f;
            if (bias) { bx = bias[c0]; by = bias[c0 + 1]; }
            float v0 = acc[mi][nj][0] + bx, v1 = acc[mi][nj][1] + by;
            float v2 = acc[mi][nj][2] + bx, v3 = acc[mi][nj][3] + by;
            if (RELU) {
                v0 = fmaxf(v0, 0.f); v1 = fmaxf(v1, 0.f);
                v2 = fmaxf(v2, 0.f); v3 = fmaxf(v3, 0.f);
            }
            if (OUTH) {
                __half* Ch = (__half*)Cv;
                *(__half2*)(Ch + (size_t)r0 * N + c0)       = __floats2half2_rn(v0, v1);
                *(__half2*)(Ch + (size_t)(r0 + 8) * N + c0) = __floats2half2_rn(v2, v3);
            } else {
                *(float2*)(Cf + (size_t)r0 * N + c0)       = make_float2(v0, v1);
                *(float2*)(Cf + (size_t)(r0 + 8) * N + c0) = make_float2(v2, v3);
            }
        }
    }
}

// ---------------------------------------------------------------------------
// out[i] = half(in[i])  (8 floats per thread)
// ---------------------------------------------------------------------------
__global__ void f2h_kernel(const float* __restrict__ in, __half* __restrict__ out) {
    const int i = blockIdx.x * blockDim.x + threadIdx.x;
    float4 v0 = ((const float4*)in)[2 * i];
    float4 v1 = ((const float4*)in)[2 * i + 1];
    __half2 h0 = __floats2half2_rn(v0.x, v0.y);
    __half2 h1 = __floats2half2_rn(v0.z, v0.w);
    __half2 h2 = __floats2half2_rn(v1.x, v1.y);
    __half2 h3 = __floats2half2_rn(v1.z, v1.w);
    __half2* o = (__half2*)out + 4 * i;
    o[0] = h0; o[1] = h1; o[2] = h2; o[3] = h3;
}

// ---------------------------------------------------------------------------
// c[i] = half(p0[i]+p1[i]+p2[i]+p3[i])  (split-K=4 combine for Wvo)
// ---------------------------------------------------------------------------
__global__ void comb4h_kernel(const float* __restrict__ p, __half* __restrict__ c) {
    const int i = blockIdx.x * blockDim.x + threadIdx.x;
    const size_t st = (size_t)DM * DM / 4;     // in float4 units
    float4 v0 = ((const float4*)p)[i];
    float4 v1 = ((const float4*)p)[i + st];
    float4 v2 = ((const float4*)p)[i + 2 * st];
    float4 v3 = ((const float4*)p)[i + 3 * st];
    float a = (v0.x + v1.x) + (v2.x + v3.x);
    float b = (v0.y + v1.y) + (v2.y + v3.y);
    float d = (v0.z + v1.z) + (v2.z + v3.z);
    float e = (v0.w + v1.w) + (v2.w + v3.w);
    ((__half2*)c)[2 * i]     = __floats2half2_rn(a, b);
    ((__half2*)c)[2 * i + 1] = __floats2half2_rn(d, e);
}

// ---------------------------------------------------------------------------
// bvo = bv @ Wo + bo, 64-way k-split (deterministic, f32)
// ---------------------------------------------------------------------------
__global__ void bvo_part_kernel(const float* __restrict__ bv, const float* __restrict__ Wo,
                                float* __restrict__ part) {
    const int n = blockIdx.x * 128 + threadIdx.x;
    const int kc = blockIdx.y;
    float s = 0.f;
#pragma unroll
    for (int k = kc * 16; k < kc * 16 + 16; ++k)
        s += bv[k] * Wo[(size_t)k * DM + n];
    part[kc * DM + n] = s;
}
__global__ void bvo_comb_kernel(const float* __restrict__ part, const float* __restrict__ bo,
                                float* __restrict__ bvo) {
    const int n = blockIdx.x * 256 + threadIdx.x;
    float s = bo[n];
#pragma unroll
    for (int j = 0; j < 64; ++j) s += part[j * DM + n];
    bvo[n] = s;
}

// ---------------------------------------------------------------------------
// LayerNorm(res[row] + add[row]) * gamma + beta over rows of length DM.
// RHALF/AHALF select residual/addend dtype. Writes f32 out and/or half out_h.
// All statistics and math in f32.
// ---------------------------------------------------------------------------
template <int RHALF, int AHALF>
__global__ __launch_bounds__(256)
void add_ln_kernel(const void* __restrict__ res, const void* __restrict__ add,
                   const float* __restrict__ gamma, const float* __restrict__ beta,
                   float* __restrict__ out, __half* __restrict__ out_h) {
    const int row = blockIdx.x;
    const int t = threadIdx.x;
    float r0, r1, r2, r3, a0, a1, a2, a3;
    if (RHALF) {
        const __half2* rp = (const __half2*)res + (size_t)row * (DM / 2) + 2 * t;
        float2 p0 = __half22float2(rp[0]);
        float2 p1 = __half22float2(rp[1]);
        r0 = p0.x; r1 = p0.y; r2 = p1.x; r3 = p1.y;
    } else {
        const float4 r = ((const float4*)res)[(size_t)row * (DM / 4) + t];
        r0 = r.x; r1 = r.y; r2 = r.z; r3 = r.w;
    }
    if (AHALF) {
        const __half2* ap = (const __half2*)add + (size_t)row * (DM / 2) + 2 * t;
        float2 p0 = __half22float2(ap[0]);
        float2 p1 = __half22float2(ap[1]);
        a0 = p0.x; a1 = p0.y; a2 = p1.x; a3 = p1.y;
    } else {
        const float4 a = ((const float4*)add)[(size_t)row * (DM / 4) + t];
        a0 = a.x; a1 = a.y; a2 = a.z; a3 = a.w;
    }
    float v0 = r0 + a0, v1 = r1 + a1, v2 = r2 + a2, v3 = r3 + a3;

    float s  = v0 + v1 + v2 + v3;
    float ss = v0 * v0 + v1 * v1 + v2 * v2 + v3 * v3;
#pragma unroll
    for (int o = 16; o > 0; o >>= 1) {
        s  += __shfl_xor_sync(0xFFFFFFFFu, s, o);
        ss += __shfl_xor_sync(0xFFFFFFFFu, ss, o);
    }
    __shared__ float sh_s[8], sh_ss[8];
    const int w = t >> 5, l = t & 31;
    if (l == 0) { sh_s[w] = s; sh_ss[w] = ss; }
    __syncthreads();
    if (w == 0) {
        s  = (l < 8) ? sh_s[l]  : 0.f;
        ss = (l < 8) ? sh_ss[l] : 0.f;
#pragma unroll
        for (int o = 4; o > 0; o >>= 1) {
            s  += __shfl_xor_sync(0xFFFFFFFFu, s, o);
            ss += __shfl_xor_sync(0xFFFFFFFFu, ss, o);
        }
        if (l == 0) { sh_s[0] = s; sh_ss[0] = ss; }
    }
    __syncthreads();
    const float mean = sh_s[0] * (1.f / DM);
    const float var  = sh_ss[0] * (1.f / DM) - mean * mean;
    const float inv  = rsqrtf(var + EPS);

    const float4 gg = ((const float4*)gamma)[t];
    const float4 bb = ((const float4*)beta)[t];
    float o0 = (v0 - mean) * inv * gg.x + bb.x;
    float o1 = (v1 - mean) * inv * gg.y + bb.y;
    float o2 = (v2 - mean) * inv * gg.z + bb.z;
    float o3 = (v3 - mean) * inv * gg.w + bb.w;
    if (out)
        ((float4*)(out + (size_t)row * DM))[t] = make_float4(o0, o1, o2, o3);
    if (out_h) {
        __half2* oh = (__half2*)(out_h + (size_t)row * DM);
        oh[2 * t]     = __floats2half2_rn(o0, o1);
        oh[2 * t + 1] = __floats2half2_rn(o2, o3);
    }
}

// ---------------------------------------------------------------------------
// Launch. Diagonal-only mask => attention == V projection. Layer reduces to:
//   attn = x @ (Wv@Wo) + (bv@Wo + bo)
//   h    = LN(x + attn; g1, beta1)
//   out  = LN(h + relu(h@W1+b1)@W2 + b2; g2, beta2)
// Two half-row pipelines (main + s1) + weight-conversion (s2) + bvo (s3).
// Residual-chain intermediates (attn, h, ff2) stored in fp16; statistics f32.
// ---------------------------------------------------------------------------
extern "C" void kernel_launch(void* const* d_in, const int* in_sizes, int n_in,
                              void* d_out, int out_size) {
    const float* x   = (const float*)d_in[0];
    const float* Wv  = (const float*)d_in[6];
    const float* bv  = (const float*)d_in[7];
    const float* Wo  = (const float*)d_in[8];
    const float* bo  = (const float*)d_in[9];
    const float* W1  = (const float*)d_in[10];
    const float* b1  = (const float*)d_in[11];
    const float* W2  = (const float*)d_in[12];
    const float* b2  = (const float*)d_in[13];
    const float* g1  = (const float*)d_in[14];
    const float* be1 = (const float*)d_in[15];
    const float* g2  = (const float*)d_in[16];
    const float* be2 = (const float*)d_in[17];
    float* out = (float*)d_out;

    __half *xh, *Wvh, *Woh, *W1h, *W2h, *Wvoh, *hh, *ffh, *ff2h;
    float *bvo, *bvop, *attn;
    cudaGetSymbolAddress((void**)&xh,   g_xh);
    cudaGetSymbolAddress((void**)&Wvh,  g_Wvh);
    cudaGetSymbolAddress((void**)&Woh,  g_Woh);
    cudaGetSymbolAddress((void**)&W1h,  g_W1h);
    cudaGetSymbolAddress((void**)&W2h,  g_W2h);
    cudaGetSymbolAddress((void**)&Wvoh, g_Wvoh);
    cudaGetSymbolAddress((void**)&hh,   g_hh);
    cudaGetSymbolAddress((void**)&ffh,  g_ffh);
    cudaGetSymbolAddress((void**)&ff2h, g_ff2h);
    cudaGetSymbolAddress((void**)&bvo,  g_bvo);
    cudaGetSymbolAddress((void**)&bvop, g_bvop);
    cudaGetSymbolAddress((void**)&attn, g_attn);
    __half* attnh = (__half*)attn;      // fold partials consumed before attn writes

    static bool init_done = false;
    static cudaStream_t s1, s2, s3;
    static cudaEvent_t ev_root, ev_x, ev_w12, ev_bvo, ev_wvo, ev_h1;
    if (!init_done) {
        cudaFuncSetAttribute(hgemm<0, 1, 0>, cudaFuncAttributeMaxDynamicSharedMemorySize, SMEM_TOTAL);
        cudaFuncSetAttribute(hgemm<0, 1, 1>, cudaFuncAttributeMaxDynamicSharedMemorySize, SMEM_TOTAL);
        cudaFuncSetAttribute(hgemm<1, 1, 1>, cudaFuncAttributeMaxDynamicSharedMemorySize, SMEM_TOTAL);
        cudaFuncSetAttribute(hgemm<0, 4, 0>, cudaFuncAttributeMaxDynamicSharedMemorySize, SMEM_TOTAL);
        cudaStreamCreateWithFlags(&s1, cudaStreamNonBlocking);
        cudaStreamCreateWithFlags(&s2, cudaStreamNonBlocking);
        cudaStreamCreateWithFlags(&s3, cudaStreamNonBlocking);
        cudaEventCreateWithFlags(&ev_root, cudaEventDisableTiming);
        cudaEventCreateWithFlags(&ev_x,    cudaEventDisableTiming);
        cudaEventCreateWithFlags(&ev_w12,  cudaEventDisableTiming);
        cudaEventCreateWithFlags(&ev_bvo,  cudaEventDisableTiming);
        cudaEventCreateWithFlags(&ev_wvo,  cudaEventDisableTiming);
        cudaEventCreateWithFlags(&ev_h1,   cudaEventDisableTiming);
        init_done = true;
    }

    const size_t rd = (size_t)HROWS * DM;   // half offset in DM-wide tensors
    const size_t rf = (size_t)HROWS * FF;   // half offset in FF-wide tensors

    // ---- fork ----
    cudaEventRecord(ev_root, 0);
    cudaStreamWaitEvent(s1, ev_root, 0);
    cudaStreamWaitEvent(s2, ev_root, 0);
    cudaStreamWaitEvent(s3, ev_root, 0);

    // s2: FFN weight conversions (needed by FFN1/FFN2)
    f2h_kernel<<<(DM * FF / 8) / 256, 256, 0, s2>>>(W1, W1h);
    f2h_kernel<<<(FF * DM / 8) / 256, 256, 0, s2>>>(W2, W2h);
    cudaEventRecord(ev_w12, s2);

    // s3: bvo = bv @ Wo + bo (64-way k-split, ~3us)
    bvo_part_kernel<<<dim3(DM / 128, 64), 128, 0, s3>>>(bv, Wo, bvop);
    bvo_comb_kernel<<<DM / 256, 256, 0, s3>>>(bvop, bo, bvo);
    cudaEventRecord(ev_bvo, s3);

    // s1: full x conversion (overlaps fold), then half-1 pipeline
    f2h_kernel<<<(MROWS * DM / 8) / 256, 256, 0, s1>>>(x, xh);
    cudaEventRecord(ev_x, s1);

    // main: Wv/Wo conversion, Wvoh = half(Wv @ Wo) via split-K=4 (scratch g_attn)
    f2h_kernel<<<(DM * DM / 8) / 256, 256>>>(Wv, Wvh);
    f2h_kernel<<<(DM * DM / 8) / 256, 256>>>(Wo, Woh);
    hgemm<0, 4, 0><<<dim3(DM / 128, DM / 128, 4), 256, SMEM_TOTAL>>>(
        Wvh, Woh, nullptr, attn, DM, DM, DM);
    comb4h_kernel<<<(DM * DM / 4) / 256, 256>>>(attn, Wvoh);
    cudaEventRecord(ev_wvo, 0);

    // ---- half-1 pipeline on s1 (rows HROWS..MROWS) ----
    cudaStreamWaitEvent(s1, ev_wvo, 0);
    cudaStreamWaitEvent(s1, ev_bvo, 0);
    hgemm<0, 1, 1><<<dim3(DM / 128, HROWS / 128), 256, SMEM_TOTAL, s1>>>(
        xh + rd, Wvoh, bvo, attnh + rd, HROWS, DM, DM);
    add_ln_kernel<0, 1><<<HROWS, 256, 0, s1>>>(
        x + rd, attnh + rd, g1, be1, nullptr, hh + rd);
    cudaStreamWaitEvent(s1, ev_w12, 0);
    hgemm<1, 1, 1><<<dim3(FF / 128, HROWS / 128), 256, SMEM_TOTAL, s1>>>(
        hh + rd, W1h, b1, ffh + rf, HROWS, FF, DM);
    hgemm<0, 1, 1><<<dim3(DM / 128, HROWS / 128), 256, SMEM_TOTAL, s1>>>(
        ffh + rf, W2h, b2, ff2h + rd, HROWS, DM, FF);
    add_ln_kernel<1, 1><<<HROWS, 256, 0, s1>>>(
        hh + rd, ff2h + rd, g2, be2, out + rd, nullptr);
    cudaEventRecord(ev_h1, s1);

    // ---- half-0 pipeline on main (rows 0..HROWS) ----
    cudaStreamWaitEvent(0, ev_x, 0);
    cudaStreamWaitEvent(0, ev_bvo, 0);
    hgemm<0, 1, 1><<<dim3(DM / 128, HROWS / 128), 256, SMEM_TOTAL>>>(
        xh, Wvoh, bvo, attnh, HROWS, DM, DM);
    add_ln_kernel<0, 1><<<HROWS, 256>>>(x, attnh, g1, be1, nullptr, hh);
    cudaStreamWaitEvent(0, ev_w12, 0);
    hgemm<1, 1, 1><<<dim3(FF / 128, HROWS / 128), 256, SMEM_TOTAL>>>(
        hh, W1h, b1, ffh, HROWS, FF, DM);
    hgemm<0, 1, 1><<<dim3(DM / 128, HROWS / 128), 256, SMEM_TOTAL>>>(
        ffh, W2h, b2, ff2h, HROWS, DM, FF);
    add_ln_kernel<1, 1><<<HROWS, 256>>>(hh, ff2h, g2, be2, out, nullptr);

    // ---- join ----
    cudaStreamWaitEvent(0, ev_h1, 0);
}

// round 13
// speedup vs baseline: 1.3602x; 1.1202x over previous
#include <cuda_runtime.h>
#include <cuda_fp16.h>
#include <cstdint>
#include <cstddef>

// Problem constants
#define DM 1024
#define FF 4096
#define MROWS 4096          // B*S = 2*2048
#define HROWS 2048          // rows per half-pipeline
#define EPS 1e-5f

// ---------------------------------------------------------------------------
// Scratch (static device globals; no runtime allocation)
// ---------------------------------------------------------------------------
__device__ __half g_xh[MROWS * DM];     // half(x)               (8 MB)
__device__ __half g_Wvh[DM * DM];       // half(Wv)              (2 MB)
__device__ __half g_Woh[DM * DM];       // half(Wo)              (2 MB)
__device__ __half g_W1h[DM * FF];       // half(W1)              (8 MB)
__device__ __half g_W2h[FF * DM];       // half(W2)              (8 MB)
__device__ __half g_Wvoh[DM * DM];      // half(Wv@Wo)           (2 MB)
__device__ float  g_bvo[DM];            // bv @ Wo + bo
__device__ float  g_bvop[64 * DM];      // bvo k-split partials
__device__ float  g_attn[4 * DM * DM];  // fold split-K f32 partials; then attn (half view) (16 MB)
__device__ __half g_hh[MROWS * DM];     // LN1 output (half)     (8 MB)
__device__ __half g_ffh[MROWS * FF];    // relu(h@W1+b1) half    (32 MB)
__device__ __half g_ff2h[MROWS * DM];   // ff@W2+b2 (half)       (8 MB)

// ---------------------------------------------------------------------------
// helpers
// ---------------------------------------------------------------------------
__device__ __forceinline__ uint32_t smem_u32(const void* p) {
    uint32_t a;
    asm("{ .reg .u64 t; cvta.to.shared.u64 t, %1; cvt.u32.u64 %0, t; }"
        : "=r"(a) : "l"(p));
    return a;
}

__device__ __forceinline__ void cp16(uint32_t s, const void* g) {
    asm volatile("cp.async.cg.shared.global [%0], [%1], 16;" :: "r"(s), "l"(g) : "memory");
}

// SMEM geometry (halfs). Padding keeps ldmatrix conflict-free.
#define ASTR 40
#define BSTR 136
#define ABYTES (128 * ASTR * 2)             // 10240
#define BBYTES (32 * BSTR * 2)              // 8704
#define STAGEB (ABYTES + BBYTES)            // 18944
#define NSTAGE 4
#define SMEM_TOTAL (NSTAGE * STAGEB)        // 75776  (x2 CTAs/SM = 151552)

// ---------------------------------------------------------------------------
// fp16 mma.sync GEMM: C[M,N] = A[M,K] @ B[K,N] (+ bias[N]) (+ReLU)
// Tile 128x128, BK=32. 128 threads = 4 warps (2 M x 2 N), warp tile 64x64
// = 4x8 m16n8k16 MMAs (8 LDSM : 32 MMA per k16 step).
// 4-stage cp.async pipeline (3 in flight), 2 CTAs/SM.
// NSPLIT>1: blockIdx.z selects K-chunk and a distinct f32 output buffer.
// ---------------------------------------------------------------------------
template <int RELU, int NSPLIT, int OUTH>
__global__ __launch_bounds__(128, 2)
void hgemm(const __half* __restrict__ A, const __half* __restrict__ B,
           const float* __restrict__ bias, void* __restrict__ Cv,
           int M, int N, int K) {
    extern __shared__ __align__(16) char smem_raw[];
    const uint32_t sbase = smem_u32(smem_raw);

    int k0g = 0, klen = K;
    float* Cf = (float*)Cv;
    if (NSPLIT > 1) {
        klen = K / NSPLIT;
        k0g = blockIdx.z * klen;
        Cf += (size_t)blockIdx.z * M * N;
    }

    const int tid  = threadIdx.x;
    const int wid  = tid >> 5, lane = tid & 31;
    const int g    = lane >> 2, tig = lane & 3;
    const int wm   = wid >> 1, wn = wid & 1;        // 2 x 2 warp grid
    const int bm   = blockIdx.y * 128, bn = blockIdx.x * 128;
    const int nk   = klen >> 5;

    // producer: A 128x32 halfs = 512 x16B chunks; B 32x128 halfs = 512 chunks
    auto load_stage = [&](int kt, int st) {
        const uint32_t sa = sbase + (uint32_t)st * STAGEB;
        const uint32_t sb = sa + ABYTES;
        const int kk = k0g + (kt << 5);
#pragma unroll
        for (int i = 0; i < 4; ++i) {
            int c = tid + i * 128;
            int r = c >> 2, s = c & 3;                 // row 0..127, seg 0..3 (8 halfs)
            cp16(sa + (uint32_t)(r * (ASTR * 2) + s * 16),
                 A + (size_t)(bm + r) * K + kk + s * 8);
        }
#pragma unroll
        for (int i = 0; i < 4; ++i) {
            int c = tid + i * 128;
            int r = c >> 4, s = c & 15;                // row 0..31, seg 0..15
            cp16(sb + (uint32_t)(r * (BSTR * 2) + s * 16),
                 B + (size_t)(kk + r) * N + bn + s * 8);
        }
        asm volatile("cp.async.commit_group;" ::: "memory");
    };

    const uint32_t a_row  = (uint32_t)(lane & 15);
    const uint32_t a_colk = (uint32_t)((lane >> 4) * 8);
    const uint32_t b_krow = (uint32_t)(lane & 15);
    const uint32_t b_coln = (uint32_t)((lane >> 4) * 8);

    float acc[4][8][4];
#pragma unroll
    for (int i = 0; i < 4; ++i)
#pragma unroll
        for (int j = 0; j < 8; ++j)
#pragma unroll
            for (int q = 0; q < 4; ++q) acc[i][j][q] = 0.f;

    load_stage(0, 0);
    load_stage(1, 1);
    load_stage(2, 2);

    for (int kt = 0; kt < nk; ++kt) {
        if (kt < nk - 2)       asm volatile("cp.async.wait_group 2;" ::: "memory");
        else if (kt == nk - 2) asm volatile("cp.async.wait_group 1;" ::: "memory");
        else                   asm volatile("cp.async.wait_group 0;" ::: "memory");
        __syncthreads();

        const uint32_t sa = sbase + (uint32_t)(kt & 3) * STAGEB;
        const uint32_t sb = sa + ABYTES;

#pragma unroll
        for (int ks = 0; ks < 2; ++ks) {               // two k16 steps per BK=32
            uint32_t a[4][4], b[8][2];
#pragma unroll
            for (int mi = 0; mi < 4; ++mi) {
                const uint32_t addr = sa +
                    ((uint32_t)(wm * 64 + mi * 16) + a_row) * (ASTR * 2) +
                    ((uint32_t)(ks * 16) + a_colk) * 2;
                asm volatile(
                    "ldmatrix.sync.aligned.m8n8.x4.shared.b16 {%0,%1,%2,%3}, [%4];"
                    : "=r"(a[mi][0]), "=r"(a[mi][1]), "=r"(a[mi][2]), "=r"(a[mi][3])
                    : "r"(addr));
            }
#pragma unroll
            for (int njp = 0; njp < 4; ++njp) {        // each x4.trans covers 2 nj
                const uint32_t addr = sb +
                    ((uint32_t)(ks * 16) + b_krow) * (BSTR * 2) +
                    ((uint32_t)(wn * 64 + njp * 16) + b_coln) * 2;
                asm volatile(
                    "ldmatrix.sync.aligned.m8n8.x4.trans.shared.b16 {%0,%1,%2,%3}, [%4];"
                    : "=r"(b[njp * 2][0]), "=r"(b[njp * 2][1]),
                      "=r"(b[njp * 2 + 1][0]), "=r"(b[njp * 2 + 1][1])
                    : "r"(addr));
            }
#pragma unroll
            for (int mi = 0; mi < 4; ++mi)
#pragma unroll
                for (int nj = 0; nj < 8; ++nj)
                    asm volatile(
                        "mma.sync.aligned.m16n8k16.row.col.f32.f16.f16.f32 "
                        "{%0,%1,%2,%3}, {%4,%5,%6,%7}, {%8,%9}, {%0,%1,%2,%3};"
                        : "+f"(acc[mi][nj][0]), "+f"(acc[mi][nj][1]),
                          "+f"(acc[mi][nj][2]), "+f"(acc[mi][nj][3])
                        : "r"(a[mi][0]), "r"(a[mi][1]), "r"(a[mi][2]), "r"(a[mi][3]),
                          "r"(b[nj][0]), "r"(b[nj][1]));
        }
        if (kt + 3 < nk) load_stage(kt + 3, (kt + 3) & 3);
    }

    // epilogue
#pragma unroll
    for (int mi = 0; mi < 4; ++mi) {
        const int r0 = bm + wm * 64 + mi * 16 + g;
#pragma unroll
        for (int nj = 0; nj < 8; ++nj) {
            const int c0 = bn + wn * 64 + nj * 8 + tig * 2;
            float bx = 0.f, by = 0.f;
            if (bias) { bx = bias[c0]; by = bias[c0 + 1]; }
            float v0 = acc[mi][nj][0] + bx, v1 = acc[mi][nj][1] + by;
            float v2 = acc[mi][nj][2] + bx, v3 = acc[mi][nj][3] + by;
            if (RELU) {
                v0 = fmaxf(v0, 0.f); v1 = fmaxf(v1, 0.f);
                v2 = fmaxf(v2, 0.f); v3 = fmaxf(v3, 0.f);
            }
            if (OUTH) {
                __half* Ch = (__half*)Cv;
                *(__half2*)(Ch + (size_t)r0 * N + c0)       = __floats2half2_rn(v0, v1);
                *(__half2*)(Ch + (size_t)(r0 + 8) * N + c0) = __floats2half2_rn(v2, v3);
            } else {
                *(float2*)(Cf + (size_t)r0 * N + c0)       = make_float2(v0, v1);
                *(float2*)(Cf + (size_t)(r0 + 8) * N + c0) = make_float2(v2, v3);
            }
        }
    }
}

// ---------------------------------------------------------------------------
// out[i] = half(in[i])  (8 floats per thread)
// ---------------------------------------------------------------------------
__global__ void f2h_kernel(const float* __restrict__ in, __half* __restrict__ out) {
    const int i = blockIdx.x * blockDim.x + threadIdx.x;
    float4 v0 = ((const float4*)in)[2 * i];
    float4 v1 = ((const float4*)in)[2 * i + 1];
    __half2 h0 = __floats2half2_rn(v0.x, v0.y);
    __half2 h1 = __floats2half2_rn(v0.z, v0.w);
    __half2 h2 = __floats2half2_rn(v1.x, v1.y);
    __half2 h3 = __floats2half2_rn(v1.z, v1.w);
    __half2* o = (__half2*)out + 4 * i;
    o[0] = h0; o[1] = h1; o[2] = h2; o[3] = h3;
}

// ---------------------------------------------------------------------------
// c[i] = half(p0[i]+p1[i]+p2[i]+p3[i])  (split-K=4 combine for Wvo)
// ---------------------------------------------------------------------------
__global__ void comb4h_kernel(const float* __restrict__ p, __half* __restrict__ c) {
    const int i = blockIdx.x * blockDim.x + threadIdx.x;
    const size_t st = (size_t)DM * DM / 4;     // in float4 units
    float4 v0 = ((const float4*)p)[i];
    float4 v1 = ((const float4*)p)[i + st];
    float4 v2 = ((const float4*)p)[i + 2 * st];
    float4 v3 = ((const float4*)p)[i + 3 * st];
    float a = (v0.x + v1.x) + (v2.x + v3.x);
    float b = (v0.y + v1.y) + (v2.y + v3.y);
    float d = (v0.z + v1.z) + (v2.z + v3.z);
    float e = (v0.w + v1.w) + (v2.w + v3.w);
    ((__half2*)c)[2 * i]     = __floats2half2_rn(a, b);
    ((__half2*)c)[2 * i + 1] = __floats2half2_rn(d, e);
}

// ---------------------------------------------------------------------------
// bvo = bv @ Wo + bo, 64-way k-split (deterministic, f32)
// ---------------------------------------------------------------------------
__global__ void bvo_part_kernel(const float* __restrict__ bv, const float* __restrict__ Wo,
                                float* __restrict__ part) {
    const int n = blockIdx.x * 128 + threadIdx.x;
    const int kc = blockIdx.y;
    float s = 0.f;
#pragma unroll
    for (int k = kc * 16; k < kc * 16 + 16; ++k)
        s += bv[k] * Wo[(size_t)k * DM + n];
    part[kc * DM + n] = s;
}
__global__ void bvo_comb_kernel(const float* __restrict__ part, const float* __restrict__ bo,
                                float* __restrict__ bvo) {
    const int n = blockIdx.x * 256 + threadIdx.x;
    float s = bo[n];
#pragma unroll
    for (int j = 0; j < 64; ++j) s += part[j * DM + n];
    bvo[n] = s;
}

// ---------------------------------------------------------------------------
// LayerNorm(res[row] + add[row]) * gamma + beta over rows of length DM.
// RHALF/AHALF select residual/addend dtype. Writes f32 out and/or half out_h.
// All statistics and math in f32.
// ---------------------------------------------------------------------------
template <int RHALF, int AHALF>
__global__ __launch_bounds__(256)
void add_ln_kernel(const void* __restrict__ res, const void* __restrict__ add,
                   const float* __restrict__ gamma, const float* __restrict__ beta,
                   float* __restrict__ out, __half* __restrict__ out_h) {
    const int row = blockIdx.x;
    const int t = threadIdx.x;
    float r0, r1, r2, r3, a0, a1, a2, a3;
    if (RHALF) {
        const __half2* rp = (const __half2*)res + (size_t)row * (DM / 2) + 2 * t;
        float2 p0 = __half22float2(rp[0]);
        float2 p1 = __half22float2(rp[1]);
        r0 = p0.x; r1 = p0.y; r2 = p1.x; r3 = p1.y;
    } else {
        const float4 r = ((const float4*)res)[(size_t)row * (DM / 4) + t];
        r0 = r.x; r1 = r.y; r2 = r.z; r3 = r.w;
    }
    if (AHALF) {
        const __half2* ap = (const __half2*)add + (size_t)row * (DM / 2) + 2 * t;
        float2 p0 = __half22float2(ap[0]);
        float2 p1 = __half22float2(ap[1]);
        a0 = p0.x; a1 = p0.y; a2 = p1.x; a3 = p1.y;
    } else {
        const float4 a = ((const float4*)add)[(size_t)row * (DM / 4) + t];
        a0 = a.x; a1 = a.y; a2 = a.z; a3 = a.w;
    }
    float v0 = r0 + a0, v1 = r1 + a1, v2 = r2 + a2, v3 = r3 + a3;

    float s  = v0 + v1 + v2 + v3;
    float ss = v0 * v0 + v1 * v1 + v2 * v2 + v3 * v3;
#pragma unroll
    for (int o = 16; o > 0; o >>= 1) {
        s  += __shfl_xor_sync(0xFFFFFFFFu, s, o);
        ss += __shfl_xor_sync(0xFFFFFFFFu, ss, o);
    }
    __shared__ float sh_s[8], sh_ss[8];
    const int w = t >> 5, l = t & 31;
    if (l == 0) { sh_s[w] = s; sh_ss[w] = ss; }
    __syncthreads();
    if (w == 0) {
        s  = (l < 8) ? sh_s[l]  : 0.f;
        ss = (l < 8) ? sh_ss[l] : 0.f;
#pragma unroll
        for (int o = 4; o > 0; o >>= 1) {
            s  += __shfl_xor_sync(0xFFFFFFFFu, s, o);
            ss += __shfl_xor_sync(0xFFFFFFFFu, ss, o);
        }
        if (l == 0) { sh_s[0] = s; sh_ss[0] = ss; }
    }
    __syncthreads();
    const float mean = sh_s[0] * (1.f / DM);
    const float var  = sh_ss[0] * (1.f / DM) - mean * mean;
    const float inv  = rsqrtf(var + EPS);

    const float4 gg = ((const float4*)gamma)[t];
    const float4 bb = ((const float4*)beta)[t];
    float o0 = (v0 - mean) * inv * gg.x + bb.x;
    float o1 = (v1 - mean) * inv * gg.y + bb.y;
    float o2 = (v2 - mean) * inv * gg.z + bb.z;
    float o3 = (v3 - mean) * inv * gg.w + bb.w;
    if (out)
        ((float4*)(out + (size_t)row * DM))[t] = make_float4(o0, o1, o2, o3);
    if (out_h) {
        __half2* oh = (__half2*)(out_h + (size_t)row * DM);
        oh[2 * t]     = __floats2half2_rn(o0, o1);
        oh[2 * t + 1] = __floats2half2_rn(o2, o3);
    }
}

// ---------------------------------------------------------------------------
// Launch. Diagonal-only mask => attention == V projection. Layer reduces to:
//   attn = x @ (Wv@Wo) + (bv@Wo + bo)
//   h    = LN(x + attn; g1, beta1)
//   out  = LN(h + relu(h@W1+b1)@W2 + b2; g2, beta2)
// Two half-row pipelines (main + s1) + weight-conversion (s2) + bvo (s3).
// Residual-chain intermediates stored in fp16; statistics f32.
// ---------------------------------------------------------------------------
extern "C" void kernel_launch(void* const* d_in, const int* in_sizes, int n_in,
                              void* d_out, int out_size) {
    const float* x   = (const float*)d_in[0];
    const float* Wv  = (const float*)d_in[6];
    const float* bv  = (const float*)d_in[7];
    const float* Wo  = (const float*)d_in[8];
    const float* bo  = (const float*)d_in[9];
    const float* W1  = (const float*)d_in[10];
    const float* b1  = (const float*)d_in[11];
    const float* W2  = (const float*)d_in[12];
    const float* b2  = (const float*)d_in[13];
    const float* g1  = (const float*)d_in[14];
    const float* be1 = (const float*)d_in[15];
    const float* g2  = (const float*)d_in[16];
    const float* be2 = (const float*)d_in[17];
    float* out = (float*)d_out;

    __half *xh, *Wvh, *Woh, *W1h, *W2h, *Wvoh, *hh, *ffh, *ff2h;
    float *bvo, *bvop, *attn;
    cudaGetSymbolAddress((void**)&xh,   g_xh);
    cudaGetSymbolAddress((void**)&Wvh,  g_Wvh);
    cudaGetSymbolAddress((void**)&Woh,  g_Woh);
    cudaGetSymbolAddress((void**)&W1h,  g_W1h);
    cudaGetSymbolAddress((void**)&W2h,  g_W2h);
    cudaGetSymbolAddress((void**)&Wvoh, g_Wvoh);
    cudaGetSymbolAddress((void**)&hh,   g_hh);
    cudaGetSymbolAddress((void**)&ffh,  g_ffh);
    cudaGetSymbolAddress((void**)&ff2h, g_ff2h);
    cudaGetSymbolAddress((void**)&bvo,  g_bvo);
    cudaGetSymbolAddress((void**)&bvop, g_bvop);
    cudaGetSymbolAddress((void**)&attn, g_attn);
    __half* attnh = (__half*)attn;      // fold partials consumed before attn writes

    static bool init_done = false;
    static cudaStream_t s1, s2, s3;
    static cudaEvent_t ev_root, ev_x, ev_w12, ev_bvo, ev_wvo, ev_h1;
    if (!init_done) {
        cudaFuncSetAttribute(hgemm<0, 1, 1>, cudaFuncAttributeMaxDynamicSharedMemorySize, SMEM_TOTAL);
        cudaFuncSetAttribute(hgemm<1, 1, 1>, cudaFuncAttributeMaxDynamicSharedMemorySize, SMEM_TOTAL);
        cudaFuncSetAttribute(hgemm<0, 4, 0>, cudaFuncAttributeMaxDynamicSharedMemorySize, SMEM_TOTAL);
        cudaStreamCreateWithFlags(&s1, cudaStreamNonBlocking);
        cudaStreamCreateWithFlags(&s2, cudaStreamNonBlocking);
        cudaStreamCreateWithFlags(&s3, cudaStreamNonBlocking);
        cudaEventCreateWithFlags(&ev_root, cudaEventDisableTiming);
        cudaEventCreateWithFlags(&ev_x,    cudaEventDisableTiming);
        cudaEventCreateWithFlags(&ev_w12,  cudaEventDisableTiming);
        cudaEventCreateWithFlags(&ev_bvo,  cudaEventDisableTiming);
        cudaEventCreateWithFlags(&ev_wvo,  cudaEventDisableTiming);
        cudaEventCreateWithFlags(&ev_h1,   cudaEventDisableTiming);
        init_done = true;
    }

    const size_t rd = (size_t)HROWS * DM;   // half offset in DM-wide tensors
    const size_t rf = (size_t)HROWS * FF;   // half offset in FF-wide tensors

    // ---- fork ----
    cudaEventRecord(ev_root, 0);
    cudaStreamWaitEvent(s1, ev_root, 0);
    cudaStreamWaitEvent(s2, ev_root, 0);
    cudaStreamWaitEvent(s3, ev_root, 0);

    // s2: FFN weight conversions (needed by FFN1/FFN2)
    f2h_kernel<<<(DM * FF / 8) / 256, 256, 0, s2>>>(W1, W1h);
    f2h_kernel<<<(FF * DM / 8) / 256, 256, 0, s2>>>(W2, W2h);
    cudaEventRecord(ev_w12, s2);

    // s3: bvo = bv @ Wo + bo (64-way k-split, ~3us)
    bvo_part_kernel<<<dim3(DM / 128, 64), 128, 0, s3>>>(bv, Wo, bvop);
    bvo_comb_kernel<<<DM / 256, 256, 0, s3>>>(bvop, bo, bvo);
    cudaEventRecord(ev_bvo, s3);

    // s1: full x conversion (overlaps fold), then half-1 pipeline
    f2h_kernel<<<(MROWS * DM / 8) / 256, 256, 0, s1>>>(x, xh);
    cudaEventRecord(ev_x, s1);

    // main: Wv/Wo conversion, Wvoh = half(Wv @ Wo) via split-K=4 (scratch g_attn)
    f2h_kernel<<<(DM * DM / 8) / 256, 256>>>(Wv, Wvh);
    f2h_kernel<<<(DM * DM / 8) / 256, 256>>>(Wo, Woh);
    hgemm<0, 4, 0><<<dim3(DM / 128, DM / 128, 4), 128, SMEM_TOTAL>>>(
        Wvh, Woh, nullptr, attn, DM, DM, DM);
    comb4h_kernel<<<(DM * DM / 4) / 256, 256>>>(attn, Wvoh);
    cudaEventRecord(ev_wvo, 0);

    // ---- half-1 pipeline on s1 (rows HROWS..MROWS) ----
    cudaStreamWaitEvent(s1, ev_wvo, 0);
    cudaStreamWaitEvent(s1, ev_bvo, 0);
    hgemm<0, 1, 1><<<dim3(DM / 128, HROWS / 128), 128, SMEM_TOTAL, s1>>>(
        xh + rd, Wvoh, bvo, attnh + rd, HROWS, DM, DM);
    add_ln_kernel<0, 1><<<HROWS, 256, 0, s1>>>(
        x + rd, attnh + rd, g1, be1, nullptr, hh + rd);
    cudaStreamWaitEvent(s1, ev_w12, 0);
    hgemm<1, 1, 1><<<dim3(FF / 128, HROWS / 128), 128, SMEM_TOTAL, s1>>>(
        hh + rd, W1h, b1, ffh + rf, HROWS, FF, DM);
    hgemm<0, 1, 1><<<dim3(DM / 128, HROWS / 128), 128, SMEM_TOTAL, s1>>>(
        ffh + rf, W2h, b2, ff2h + rd, HROWS, DM, FF);
    add_ln_kernel<1, 1><<<HROWS, 256, 0, s1>>>(
        hh + rd, ff2h + rd, g2, be2, out + rd, nullptr);
    cudaEventRecord(ev_h1, s1);

    // ---- half-0 pipeline on main (rows 0..HROWS) ----
    cudaStreamWaitEvent(0, ev_x, 0);
    cudaStreamWaitEvent(0, ev_bvo, 0);
    hgemm<0, 1, 1><<<dim3(DM / 128, HROWS / 128), 128, SMEM_TOTAL>>>(
        xh, Wvoh, bvo, attnh, HROWS, DM, DM);
    add_ln_kernel<0, 1><<<HROWS, 256>>>(x, attnh, g1, be1, nullptr, hh);
    cudaStreamWaitEvent(0, ev_w12, 0);
    hgemm<1, 1, 1><<<dim3(FF / 128, HROWS / 128), 128, SMEM_TOTAL>>>(
        hh, W1h, b1, ffh, HROWS, FF, DM);
    hgemm<0, 1, 1><<<dim3(DM / 128, HROWS / 128), 128, SMEM_TOTAL>>>(
        ffh, W2h, b2, ff2h, HROWS, DM, FF);
    add_ln_kernel<1, 1><<<HROWS, 256>>>(hh, ff2h, g2, be2, out, nullptr);

    // ---- join ----
    cudaStreamWaitEvent(0, ev_h1, 0);
}